// round 2
// baseline (speedup 1.0000x reference)
#include <cuda_runtime.h>
#include <math.h>

#define NEG_INF (__int_as_float(0xff800000))

// ---------------- problem constants ----------------
#define BATCH   16
#define NFEAT   16
#define TLEN    64
#define SCL     32
#define HID     128
#define FS      4
#define NHEAD   2
#define DHEAD   64

#define H1H     61          // TLEN-3
#define H1W     29          // SCL-3
#define H2H     58
#define H2W     26
#define LSEQ    1508        // H2H*H2W
#define UTOP    40

#define K1      256         // NFEAT*FS*FS
#define K2      2048        // HID*FS*FS
#define M1      (BATCH*H1H*H1W)   // 28304
#define M2      (BATCH*LSEQ)      // 24128
#define BHCNT   (BATCH*NHEAD)     // 32

// ---------------- scratch (device globals; no runtime alloc) ----------------
__device__ float g_h1[BATCH*HID*H1H*H1W];
__device__ float g_seq[M2*HID];
__device__ float g_Q[BHCNT*LSEQ*DHEAD];
__device__ float g_K[BHCNT*LSEQ*DHEAD];
__device__ float g_V[BHCNT*LSEQ*DHEAD];
__device__ float g_ctx[M2*HID];
__device__ float g_M[BHCNT*LSEQ];
__device__ int   g_Mtop[BHCNT*UTOP];
__device__ float g_upd[BHCNT*UTOP*DHEAD];
__device__ float g_vmean[BHCNT*DHEAD];
__device__ float g_w1t[K1*HID];
__device__ float g_w2t[K2*HID];

// ---------------- helpers ----------------
__device__ __forceinline__ float warp_sum(float v) {
    v += __shfl_xor_sync(0xffffffffu, v, 16);
    v += __shfl_xor_sync(0xffffffffu, v, 8);
    v += __shfl_xor_sync(0xffffffffu, v, 4);
    v += __shfl_xor_sync(0xffffffffu, v, 2);
    v += __shfl_xor_sync(0xffffffffu, v, 1);
    return v;
}

// ---------------- weight transpose: w[oc][k] -> wT[k][oc] ----------------
__global__ void transpose_w_kernel(const float* __restrict__ w, float* __restrict__ wT, int Kdim) {
    int idx = blockIdx.x * blockDim.x + threadIdx.x;
    if (idx >= HID * Kdim) return;
    int oc = idx / Kdim;
    int k  = idx % Kdim;
    wT[k * HID + oc] = w[idx];
}

// ---------------- implicit-GEMM conv (+bias +relu) ----------------
// A = im2col(in) [M x K], B = wT [K x 128]. BM=64, BN=128, BK=16, 256 threads.
template<int ICT, int INH, int INW, int OH, int OW, bool SEQ_OUT>
__global__ void conv_gemm_kernel(const float* __restrict__ in, const float* __restrict__ wT,
                                 const float* __restrict__ bias, float* __restrict__ out,
                                 int M, int K) {
    __shared__ float As[16][64];
    __shared__ float Bs[16][128];
    const int tid = threadIdx.x;
    const int tx = tid & 15;          // col group: n = tx*8
    const int ty = tid >> 4;          // row group: m = ty*4
    const int block_m = blockIdx.x * 64;

    // Precompute A-load coordinates (m is fixed across K tiles)
    int a_ml[4], a_kl[4], a_base[4];
    bool a_ok[4];
#pragma unroll
    for (int i = 0; i < 4; i++) {
        int idx = tid + i * 256;            // 0..1023
        a_ml[i] = idx & 63;
        a_kl[i] = idx >> 6;
        int m = block_m + a_ml[i];
        a_ok[i] = (m < M);
        if (m >= M) m = 0;
        int b  = m / (OH * OW);
        int r  = m % (OH * OW);
        int oh = r / OW;
        int ow = r % OW;
        a_base[i] = ((b * ICT) * INH + oh) * INW + ow;
    }

    float acc[4][8];
#pragma unroll
    for (int i = 0; i < 4; i++)
#pragma unroll
        for (int j = 0; j < 8; j++) acc[i][j] = 0.f;

    for (int kt = 0; kt < K; kt += 16) {
#pragma unroll
        for (int i = 0; i < 4; i++) {
            int k  = kt + a_kl[i];
            int ic = k >> 4;
            int kh = (k >> 2) & 3;
            int kw = k & 3;
            As[a_kl[i]][a_ml[i]] = a_ok[i] ? in[a_base[i] + (ic * INH + kh) * INW + kw] : 0.f;
        }
#pragma unroll
        for (int i = 0; i < 8; i++) {
            int idx = tid + i * 256;        // 0..2047
            int nl = idx & 127;
            int kl = idx >> 7;
            Bs[kl][nl] = wT[(kt + kl) * HID + nl];
        }
        __syncthreads();
#pragma unroll
        for (int k = 0; k < 16; k++) {
            float4 a4 = *reinterpret_cast<const float4*>(&As[k][ty * 4]);
            float4 b0 = *reinterpret_cast<const float4*>(&Bs[k][tx * 8]);
            float4 b1 = *reinterpret_cast<const float4*>(&Bs[k][tx * 8 + 4]);
            float av[4] = {a4.x, a4.y, a4.z, a4.w};
            float bv[8] = {b0.x, b0.y, b0.z, b0.w, b1.x, b1.y, b1.z, b1.w};
#pragma unroll
            for (int i = 0; i < 4; i++)
#pragma unroll
                for (int j = 0; j < 8; j++) acc[i][j] += av[i] * bv[j];
        }
        __syncthreads();
    }

#pragma unroll
    for (int i = 0; i < 4; i++) {
        int m = block_m + ty * 4 + i;
        if (m >= M) continue;
        int b  = m / (OH * OW);
        int r  = m % (OH * OW);
        int oh = r / OW;
        int ow = r % OW;
#pragma unroll
        for (int j = 0; j < 8; j++) {
            int n = tx * 8 + j;
            float v = acc[i][j] + bias[n];
            v = fmaxf(v, 0.f);
            if (SEQ_OUT) out[m * HID + n] = v;
            else         out[((b * HID + n) * OH + oh) * OW + ow] = v;
        }
    }
}

// ---------------- linear GEMM (A [M x 128] @ W [128 x 128] + bias) ----------------
// layout 0: out[m*128+n]; layout 1: out[((b*NH+h)*L + l)*64 + d]
__global__ void linear_gemm_kernel(const float* __restrict__ A, const float* __restrict__ W,
                                   const float* __restrict__ bias, float* __restrict__ out,
                                   int M, int layout) {
    __shared__ float As[16][68];   // padded
    __shared__ float Bs[16][128];
    const int tid = threadIdx.x;
    const int tx = tid & 15;
    const int ty = tid >> 4;
    const int block_m = blockIdx.x * 64;

    float acc[4][8];
#pragma unroll
    for (int i = 0; i < 4; i++)
#pragma unroll
        for (int j = 0; j < 8; j++) acc[i][j] = 0.f;

    for (int kt = 0; kt < HID; kt += 16) {
#pragma unroll
        for (int i = 0; i < 4; i++) {
            int idx = tid + i * 256;
            int kl = idx & 15;
            int ml = idx >> 4;
            int m = block_m + ml;
            As[kl][ml] = (m < M) ? A[m * HID + kt + kl] : 0.f;
        }
#pragma unroll
        for (int i = 0; i < 8; i++) {
            int idx = tid + i * 256;
            int nl = idx & 127;
            int kl = idx >> 7;
            Bs[kl][nl] = W[(kt + kl) * HID + nl];
        }
        __syncthreads();
#pragma unroll
        for (int k = 0; k < 16; k++) {
            float av[4];
#pragma unroll
            for (int i = 0; i < 4; i++) av[i] = As[k][ty * 4 + i];
            float4 b0 = *reinterpret_cast<const float4*>(&Bs[k][tx * 8]);
            float4 b1 = *reinterpret_cast<const float4*>(&Bs[k][tx * 8 + 4]);
            float bv[8] = {b0.x, b0.y, b0.z, b0.w, b1.x, b1.y, b1.z, b1.w};
#pragma unroll
            for (int i = 0; i < 4; i++)
#pragma unroll
                for (int j = 0; j < 8; j++) acc[i][j] += av[i] * bv[j];
        }
        __syncthreads();
    }

#pragma unroll
    for (int i = 0; i < 4; i++) {
        int m = block_m + ty * 4 + i;
        if (m >= M) continue;
#pragma unroll
        for (int j = 0; j < 8; j++) {
            int n = tx * 8 + j;
            float v = acc[i][j] + bias[n];
            if (layout == 0) {
                out[m * HID + n] = v;
            } else {
                int b = m / LSEQ, l = m % LSEQ;
                int h = n >> 6,   d = n & 63;
                out[((b * NHEAD + h) * LSEQ + l) * DHEAD + d] = v;
            }
        }
    }
}

// ---------------- sampled scores -> M ----------------
__global__ void sampled_m_kernel(const float* __restrict__ Q, const float* __restrict__ K,
                                 const int* __restrict__ idxs, float* __restrict__ Mout) {
    int gwarp = (blockIdx.x * blockDim.x + threadIdx.x) >> 5;
    int lane = threadIdx.x & 31;
    if (gwarp >= BHCNT * LSEQ) return;
    int bh = gwarp / LSEQ;
    int l  = gwarp % LSEQ;
    const float* q = Q + (size_t)gwarp * DHEAD;
    float q0 = q[lane * 2], q1 = q[lane * 2 + 1];
    const float* Kb = K + (size_t)bh * LSEQ * DHEAD;
    float mx = NEG_INF, sm = 0.f;
#pragma unroll 1
    for (int u = 0; u < UTOP; u += 4) {
        float d[4];
#pragma unroll
        for (int j = 0; j < 4; j++) {
            int ki = idxs[l * UTOP + u + j];
            const float* kr = Kb + (size_t)ki * DHEAD;
            d[j] = q0 * kr[lane * 2] + q1 * kr[lane * 2 + 1];
        }
#pragma unroll
        for (int j = 0; j < 4; j++) d[j] = warp_sum(d[j]);
#pragma unroll
        for (int j = 0; j < 4; j++) { mx = fmaxf(mx, d[j]); sm += d[j]; }
    }
    if (lane == 0) Mout[gwarp] = mx - sm / (float)LSEQ;
}

// ---------------- top-40 per (b,h) ----------------
__global__ void topk_kernel(const float* __restrict__ Min, int* __restrict__ Mtop) {
    __shared__ float vals[LSEQ];
    __shared__ float rv[256];
    __shared__ int   ri[256];
    int bh = blockIdx.x;
    int tid = threadIdx.x;
    for (int j = tid; j < LSEQ; j += 256) vals[j] = Min[bh * LSEQ + j];
    __syncthreads();
    for (int it = 0; it < UTOP; it++) {
        float best = NEG_INF;
        int bi = LSEQ;
        for (int j = tid; j < LSEQ; j += 256) {
            float v = vals[j];
            if (v > best) { best = v; bi = j; }   // first occurrence kept within thread
        }
        rv[tid] = best; ri[tid] = bi;
        __syncthreads();
        for (int s = 128; s > 0; s >>= 1) {
            if (tid < s) {
                float vo = rv[tid + s]; int io = ri[tid + s];
                if (vo > rv[tid] || (vo == rv[tid] && io < ri[tid])) { rv[tid] = vo; ri[tid] = io; }
            }
            __syncthreads();
        }
        if (tid == 0) {
            Mtop[bh * UTOP + it] = ri[0];
            vals[ri[0]] = NEG_INF;
        }
        __syncthreads();
    }
}

// ---------------- V mean per (b,h) ----------------
__global__ void vmean_kernel(const float* __restrict__ V, float* __restrict__ vmean) {
    int bh = blockIdx.x;
    int d = threadIdx.x;   // 64 threads
    const float* Vb = V + (size_t)bh * LSEQ * DHEAD;
    float s = 0.f;
    for (int l = 0; l < LSEQ; l++) s += Vb[(size_t)l * DHEAD + d];
    vmean[bh * DHEAD + d] = s / (float)LSEQ;
}

// ---------------- attention over all keys for selected queries ----------------
__global__ void attn_kernel(const float* __restrict__ Q, const float* __restrict__ K,
                            const float* __restrict__ V, const int* __restrict__ Mtop,
                            float* __restrict__ upd) {
    int gwarp = (blockIdx.x * blockDim.x + threadIdx.x) >> 5;
    int lane = threadIdx.x & 31;
    if (gwarp >= BHCNT * UTOP) return;
    int bh = gwarp / UTOP;
    int l = Mtop[gwarp];
    const float* q = Q + ((size_t)bh * LSEQ + l) * DHEAD;
    float q0 = q[lane * 2], q1 = q[lane * 2 + 1];
    const float* Kb = K + (size_t)bh * LSEQ * DHEAD;
    const float* Vb = V + (size_t)bh * LSEQ * DHEAD;
    float m = NEG_INF, s = 0.f, a0 = 0.f, a1 = 0.f;
#pragma unroll 1
    for (int k0 = 0; k0 < LSEQ; k0 += 4) {
        float d[4], v0[4], v1[4];
#pragma unroll
        for (int j = 0; j < 4; j++) {
            const float* kr = Kb + (size_t)(k0 + j) * DHEAD;
            d[j] = q0 * kr[lane * 2] + q1 * kr[lane * 2 + 1];
        }
#pragma unroll
        for (int j = 0; j < 4; j++) d[j] = warp_sum(d[j]) * 0.125f;
#pragma unroll
        for (int j = 0; j < 4; j++) {
            const float* vr = Vb + (size_t)(k0 + j) * DHEAD;
            v0[j] = vr[lane * 2];
            v1[j] = vr[lane * 2 + 1];
        }
#pragma unroll
        for (int j = 0; j < 4; j++) {
            float nm = fmaxf(m, d[j]);
            float c = __expf(m - nm);
            float p = __expf(d[j] - nm);
            s = s * c + p;
            a0 = a0 * c + p * v0[j];
            a1 = a1 * c + p * v1[j];
            m = nm;
        }
    }
    float inv = 1.f / s;
    upd[(size_t)gwarp * DHEAD + lane * 2]     = a0 * inv;
    upd[(size_t)gwarp * DHEAD + lane * 2 + 1] = a1 * inv;
}

// ---------------- ctx fill (broadcast vmean) ----------------
__global__ void fill_ctx_kernel(const float* __restrict__ vmean, float* __restrict__ ctx) {
    int idx = blockIdx.x * blockDim.x + threadIdx.x;
    if (idx >= M2 * HID) return;
    int c = idx & 127;
    int m = idx >> 7;           // b*L + l
    int b = m / LSEQ;
    int h = c >> 6, d = c & 63;
    ctx[idx] = vmean[(b * NHEAD + h) * DHEAD + d];
}

// ---------------- scatter upd rows ----------------
__global__ void scatter_kernel(const float* __restrict__ upd, const int* __restrict__ Mtop,
                               float* __restrict__ ctx) {
    int idx = blockIdx.x * blockDim.x + threadIdx.x;
    if (idx >= BHCNT * UTOP * DHEAD) return;
    int d = idx & 63;
    int r = idx >> 6;         // bh*U + u
    int bh = r / UTOP;
    int b = bh / NHEAD, h = bh % NHEAD;
    int l = Mtop[r];
    ctx[((size_t)(b * LSEQ + l)) * HID + h * DHEAD + d] = upd[idx];
}

// ---------------- launch ----------------
extern "C" void kernel_launch(void* const* d_in, const int* in_sizes, int n_in,
                              void* d_out, int out_size) {
    const float* x       = (const float*)d_in[0];
    const float* conv1_w = (const float*)d_in[1];
    const float* conv1_b = (const float*)d_in[2];
    const float* conv2_w = (const float*)d_in[3];
    const float* conv2_b = (const float*)d_in[4];
    const float* wq = (const float*)d_in[5];
    const float* bq = (const float*)d_in[6];
    const float* wk = (const float*)d_in[7];
    const float* bk = (const float*)d_in[8];
    const float* wv = (const float*)d_in[9];
    const float* bv = (const float*)d_in[10];
    const float* wo = (const float*)d_in[11];
    const float* bo = (const float*)d_in[12];
    const int* index_sample = (const int*)d_in[13];
    float* out = (float*)d_out;

    float *h1, *seq, *Qp, *Kp, *Vp, *ctx, *Mv, *updv, *vmeanv, *w1t, *w2t;
    int *mtop;
    cudaGetSymbolAddress((void**)&h1, g_h1);
    cudaGetSymbolAddress((void**)&seq, g_seq);
    cudaGetSymbolAddress((void**)&Qp, g_Q);
    cudaGetSymbolAddress((void**)&Kp, g_K);
    cudaGetSymbolAddress((void**)&Vp, g_V);
    cudaGetSymbolAddress((void**)&ctx, g_ctx);
    cudaGetSymbolAddress((void**)&Mv, g_M);
    cudaGetSymbolAddress((void**)&mtop, g_Mtop);
    cudaGetSymbolAddress((void**)&updv, g_upd);
    cudaGetSymbolAddress((void**)&vmeanv, g_vmean);
    cudaGetSymbolAddress((void**)&w1t, g_w1t);
    cudaGetSymbolAddress((void**)&w2t, g_w2t);

    // weight transposes
    transpose_w_kernel<<<(HID * K1 + 255) / 256, 256>>>(conv1_w, w1t, K1);
    transpose_w_kernel<<<(HID * K2 + 255) / 256, 256>>>(conv2_w, w2t, K2);

    // conv1: x (B,16,64,32) -> h1 (B,128,61,29), relu
    conv_gemm_kernel<NFEAT, TLEN, SCL, H1H, H1W, false>
        <<<(M1 + 63) / 64, 256>>>(x, w1t, conv1_b, h1, M1, K1);

    // conv2: h1 -> seq (B*L, 128), relu
    conv_gemm_kernel<HID, H1H, H1W, H2H, H2W, true>
        <<<(M2 + 63) / 64, 256>>>(h1, w2t, conv2_b, seq, M2, K2);

    // QKV projections (strided head layout)
    linear_gemm_kernel<<<(M2 + 63) / 64, 256>>>(seq, wq, bq, Qp, M2, 1);
    linear_gemm_kernel<<<(M2 + 63) / 64, 256>>>(seq, wk, bk, Kp, M2, 1);
    linear_gemm_kernel<<<(M2 + 63) / 64, 256>>>(seq, wv, bv, Vp, M2, 1);

    // sampled scores -> M
    {
        int warps = BHCNT * LSEQ;
        int blocks = (warps + 3) / 4;
        sampled_m_kernel<<<blocks, 128>>>(Qp, Kp, index_sample, Mv);
    }

    // top-40 per (b,h)
    topk_kernel<<<BHCNT, 256>>>(Mv, mtop);

    // V mean
    vmean_kernel<<<BHCNT, 64>>>(Vp, vmeanv);

    // full attention on selected queries
    {
        int warps = BHCNT * UTOP;
        int blocks = (warps + 3) / 4;
        attn_kernel<<<blocks, 128>>>(Qp, Kp, Vp, mtop, updv);
    }

    // ctx = broadcast(vmean); ctx[mtop] = upd
    fill_ctx_kernel<<<(M2 * HID + 255) / 256, 256>>>(vmeanv, ctx);
    scatter_kernel<<<(BHCNT * UTOP * DHEAD + 255) / 256, 256>>>(updv, mtop, ctx);

    // final projection
    linear_gemm_kernel<<<(M2 + 63) / 64, 256>>>(ctx, wo, bo, out, M2, 0);
}

// round 3
// speedup vs baseline: 1.5366x; 1.5366x over previous
#include <cuda_runtime.h>
#include <math.h>

#define NEG_INF (__int_as_float(0xff800000))

// ---------------- problem constants ----------------
#define BATCH   16
#define NFEAT   16
#define TLEN    64
#define SCL     32
#define HID     128
#define FS      4
#define NHEAD   2
#define DHEAD   64

#define H1H     61
#define H1W     29
#define H2H     58
#define H2W     26
#define LSEQ    1508
#define UTOP    40

#define K1      256
#define K2      2048
#define M1      (BATCH*H1H*H1W)   // 28304
#define M2      (BATCH*LSEQ)      // 24128
#define BHCNT   (BATCH*NHEAD)     // 32

// ---------------- scratch ----------------
__device__ float g_h1[BATCH*HID*H1H*H1W];
__device__ float g_seq[M2*HID];
__device__ float g_Q[BHCNT*LSEQ*DHEAD];
__device__ float g_K[BHCNT*LSEQ*DHEAD];
__device__ float g_V[BHCNT*LSEQ*DHEAD];
__device__ float g_ctx[M2*HID];
__device__ float g_M[BHCNT*LSEQ];
__device__ int   g_Mtop[BHCNT*UTOP];
__device__ float g_upd[BHCNT*UTOP*DHEAD];
__device__ float g_vmean[BHCNT*DHEAD];
__device__ float g_w1t[K1*HID];
__device__ float g_w2t[K2*HID];
__device__ float g_part[4*M2*HID];   // split-K partials (49.4 MB, reused)

// ---------------- helpers ----------------
__device__ __forceinline__ float warp_sum(float v) {
    v += __shfl_xor_sync(0xffffffffu, v, 16);
    v += __shfl_xor_sync(0xffffffffu, v, 8);
    v += __shfl_xor_sync(0xffffffffu, v, 4);
    v += __shfl_xor_sync(0xffffffffu, v, 2);
    v += __shfl_xor_sync(0xffffffffu, v, 1);
    return v;
}

// packed fp32 FMA (Blackwell FFMA2 — only reachable via PTX fma.rn.f32x2)
__device__ __forceinline__ void ffma2(float2& c, const float2 a, const float2 b) {
    unsigned long long& c64 = reinterpret_cast<unsigned long long&>(c);
    const unsigned long long& a64 = reinterpret_cast<const unsigned long long&>(a);
    const unsigned long long& b64 = reinterpret_cast<const unsigned long long&>(b);
    asm("fma.rn.f32x2 %0, %1, %2, %0;" : "+l"(c64) : "l"(a64), "l"(b64));
}

// ---------------- weight transpose: w[oc][k] -> wT[k][oc] ----------------
__global__ void transpose_w_kernel(const float* __restrict__ w, float* __restrict__ wT, int Kdim) {
    int idx = blockIdx.x * blockDim.x + threadIdx.x;
    if (idx >= HID * Kdim) return;
    int oc = idx / Kdim;
    int k  = idx % Kdim;
    wT[k * HID + oc] = w[idx];
}

// ---------------- unified f32x2 GEMM ----------------
// C[M x 128] = A[M x K] @ B[K x 128]. BM=128, BN=128, BK=16, 256 threads, 8x8/thread.
// IM2COL: A is implicit im2col of NCHW input. SPLIT: write raw partial to part buffer.
// LAYOUT 0: out[m*128+n]; 1: QKV head layout; (conv1 NCHW handled by reduce kernel)
template<bool IM2COL, int ICT, int INH, int INW, int OHt, int OWt,
         int LAYOUT, bool RELU, bool SPLIT, int KSPL>
__global__ void __launch_bounds__(256, 2)
gemm_f32x2_kernel(const float* __restrict__ Ain, const float* __restrict__ Bw,
                  const float* __restrict__ bias, float* __restrict__ out,
                  int M, int K) {
    __shared__ __align__(16) float As[16][132];
    __shared__ __align__(16) float Bs[16][132];
    const int tid = threadIdx.x;
    const int tx = tid & 15;
    const int ty = tid >> 4;
    const int block_m = blockIdx.x * 128;
    const int kbeg = blockIdx.y * KSPL;

    // A global-load ids: lane k = tid&15, m = (tid>>4) + i*16
    const int lk = tid & 15;
    const int lm = tid >> 4;
    int abase[8];
    bool aok[8];
#pragma unroll
    for (int i = 0; i < 8; i++) {
        int m = block_m + lm + i * 16;
        aok[i] = (m < M);
        int mc = aok[i] ? m : 0;
        if (IM2COL) {
            int b = mc / (OHt * OWt);
            int r = mc % (OHt * OWt);
            abase[i] = ((b * ICT) * INH + r / OWt) * INW + (r % OWt);
        } else {
            abase[i] = mc * K;
        }
    }
    const int bn  = tid & 127;
    const int bk0 = tid >> 7;

    float2 acc[8][4];
#pragma unroll
    for (int i = 0; i < 8; i++)
#pragma unroll
        for (int j = 0; j < 4; j++) acc[i][j] = make_float2(0.f, 0.f);

    float ar[8], br[8];

    // --- load tile at kt into regs ---
    auto load_tile = [&](int kt) {
        if (IM2COL) {
            int kgl = kt + lk;
            int off = ((kgl >> 4) * INH + ((kgl >> 2) & 3)) * INW + (kgl & 3);
#pragma unroll
            for (int i = 0; i < 8; i++) ar[i] = aok[i] ? Ain[abase[i] + off] : 0.f;
        } else {
#pragma unroll
            for (int i = 0; i < 8; i++) ar[i] = aok[i] ? Ain[abase[i] + kt + lk] : 0.f;
        }
#pragma unroll
        for (int i = 0; i < 8; i++) br[i] = Bw[(kt + bk0 + i * 2) * HID + bn];
    };
    auto store_tile = [&]() {
#pragma unroll
        for (int i = 0; i < 8; i++) As[lk][lm + i * 16] = ar[i];
#pragma unroll
        for (int i = 0; i < 8; i++) Bs[bk0 + i * 2][bn] = br[i];
    };

    load_tile(kbeg);
    store_tile();
    __syncthreads();

    const int nt = KSPL / 16;
    for (int t = 0; t < nt; t++) {
        bool more = (t + 1) < nt;
        if (more) load_tile(kbeg + (t + 1) * 16);
#pragma unroll
        for (int k = 0; k < 16; k++) {
            float4 a0 = *reinterpret_cast<const float4*>(&As[k][ty * 4]);
            float4 a1 = *reinterpret_cast<const float4*>(&As[k][64 + ty * 4]);
            float4 b0 = *reinterpret_cast<const float4*>(&Bs[k][tx * 4]);
            float4 b1 = *reinterpret_cast<const float4*>(&Bs[k][64 + tx * 4]);
            float am[8] = {a0.x, a0.y, a0.z, a0.w, a1.x, a1.y, a1.z, a1.w};
            float2 bb[4] = {make_float2(b0.x, b0.y), make_float2(b0.z, b0.w),
                            make_float2(b1.x, b1.y), make_float2(b1.z, b1.w)};
#pragma unroll
            for (int i = 0; i < 8; i++) {
                float2 ad = make_float2(am[i], am[i]);
#pragma unroll
                for (int j = 0; j < 4; j++) ffma2(acc[i][j], ad, bb[j]);
            }
        }
        if (more) {
            __syncthreads();
            store_tile();
            __syncthreads();
        }
    }

    // --- epilogue ---
#pragma unroll
    for (int i = 0; i < 8; i++) {
        int m = block_m + ((i < 4) ? (ty * 4 + i) : (64 + ty * 4 + i - 4));
        if (m >= M) continue;
#pragma unroll
        for (int j = 0; j < 4; j++) {
            int n = (j < 2) ? (tx * 4 + 2 * j) : (64 + tx * 4 + 2 * (j - 2));
            float2 v = acc[i][j];
            if (SPLIT) {
                *reinterpret_cast<float2*>(&out[((size_t)blockIdx.y * M + m) * HID + n]) = v;
            } else {
                v.x += bias[n];
                v.y += bias[n + 1];
                if (RELU) { v.x = fmaxf(v.x, 0.f); v.y = fmaxf(v.y, 0.f); }
                if (LAYOUT == 0) {
                    *reinterpret_cast<float2*>(&out[(size_t)m * HID + n]) = v;
                } else {  // QKV head layout
                    int b = m / LSEQ, l = m % LSEQ;
                    int h = n >> 6, d = n & 63;
                    *reinterpret_cast<float2*>(
                        &out[((size_t)(b * NHEAD + h) * LSEQ + l) * DHEAD + d]) = v;
                }
            }
        }
    }
}

// ---------------- split-K reduce (+bias, +relu, layout) ----------------
// LAYOUT 0: row-major M x 128. LAYOUT 2: conv1 NCHW (B,128,H1H,H1W)
template<int NS, bool RELU, int LAYOUT>
__global__ void reduce_kernel(const float* __restrict__ part, const float* __restrict__ bias,
                              float* __restrict__ out, int M) {
    int idx = blockIdx.x * blockDim.x + threadIdx.x;
    if (idx >= M * HID) return;
    int n = idx & 127;
    int m = idx >> 7;
    float s = 0.f;
#pragma unroll
    for (int p = 0; p < NS; p++) s += part[(size_t)p * M * HID + idx];
    s += bias[n];
    if (RELU) s = fmaxf(s, 0.f);
    if (LAYOUT == 0) {
        out[idx] = s;
    } else {
        int b = m / (H1H * H1W);
        int r = m % (H1H * H1W);
        out[((b * HID + n) * H1H + r / H1W) * H1W + (r % H1W)] = s;
    }
}

// ---------------- sampled scores -> M ----------------
__global__ void sampled_m_kernel(const float* __restrict__ Q, const float* __restrict__ K,
                                 const int* __restrict__ idxs, float* __restrict__ Mout) {
    int gwarp = (blockIdx.x * blockDim.x + threadIdx.x) >> 5;
    int lane = threadIdx.x & 31;
    if (gwarp >= BHCNT * LSEQ) return;
    int bh = gwarp / LSEQ;
    int l  = gwarp % LSEQ;
    const float* q = Q + (size_t)gwarp * DHEAD;
    float q0 = q[lane * 2], q1 = q[lane * 2 + 1];
    const float* Kb = K + (size_t)bh * LSEQ * DHEAD;
    float mx = NEG_INF, sm = 0.f;
#pragma unroll 1
    for (int u = 0; u < UTOP; u += 4) {
        float d[4];
#pragma unroll
        for (int j = 0; j < 4; j++) {
            int ki = idxs[l * UTOP + u + j];
            const float* kr = Kb + (size_t)ki * DHEAD;
            d[j] = q0 * kr[lane * 2] + q1 * kr[lane * 2 + 1];
        }
#pragma unroll
        for (int j = 0; j < 4; j++) d[j] = warp_sum(d[j]);
#pragma unroll
        for (int j = 0; j < 4; j++) { mx = fmaxf(mx, d[j]); sm += d[j]; }
    }
    if (lane == 0) Mout[gwarp] = mx - sm / (float)LSEQ;
}

// ---------------- top-40 per (b,h) ----------------
__global__ void topk_kernel(const float* __restrict__ Min, int* __restrict__ Mtop) {
    __shared__ float vals[LSEQ];
    __shared__ float rv[256];
    __shared__ int   ri[256];
    int bh = blockIdx.x;
    int tid = threadIdx.x;
    for (int j = tid; j < LSEQ; j += 256) vals[j] = Min[bh * LSEQ + j];
    __syncthreads();
    for (int it = 0; it < UTOP; it++) {
        float best = NEG_INF;
        int bi = LSEQ;
        for (int j = tid; j < LSEQ; j += 256) {
            float v = vals[j];
            if (v > best) { best = v; bi = j; }
        }
        rv[tid] = best; ri[tid] = bi;
        __syncthreads();
        for (int s = 128; s > 0; s >>= 1) {
            if (tid < s) {
                float vo = rv[tid + s]; int io = ri[tid + s];
                if (vo > rv[tid] || (vo == rv[tid] && io < ri[tid])) { rv[tid] = vo; ri[tid] = io; }
            }
            __syncthreads();
        }
        if (tid == 0) {
            Mtop[bh * UTOP + it] = ri[0];
            vals[ri[0]] = NEG_INF;
        }
        __syncthreads();
    }
}

// ---------------- V mean per (b,h) ----------------
__global__ void vmean_kernel(const float* __restrict__ V, float* __restrict__ vmean) {
    int bh = blockIdx.x;
    int d = threadIdx.x;
    const float* Vb = V + (size_t)bh * LSEQ * DHEAD;
    float s = 0.f;
    for (int l = 0; l < LSEQ; l++) s += Vb[(size_t)l * DHEAD + d];
    vmean[bh * DHEAD + d] = s / (float)LSEQ;
}

// ---------------- attention over all keys for selected queries ----------------
__global__ void attn_kernel(const float* __restrict__ Q, const float* __restrict__ K,
                            const float* __restrict__ V, const int* __restrict__ Mtop,
                            float* __restrict__ upd) {
    int gwarp = (blockIdx.x * blockDim.x + threadIdx.x) >> 5;
    int lane = threadIdx.x & 31;
    if (gwarp >= BHCNT * UTOP) return;
    int bh = gwarp / UTOP;
    int l = Mtop[gwarp];
    const float* q = Q + ((size_t)bh * LSEQ + l) * DHEAD;
    float q0 = q[lane * 2], q1 = q[lane * 2 + 1];
    const float* Kb = K + (size_t)bh * LSEQ * DHEAD;
    const float* Vb = V + (size_t)bh * LSEQ * DHEAD;
    float m = NEG_INF, s = 0.f, a0 = 0.f, a1 = 0.f;
#pragma unroll 1
    for (int k0 = 0; k0 < LSEQ; k0 += 4) {
        float d[4], v0[4], v1[4];
#pragma unroll
        for (int j = 0; j < 4; j++) {
            const float* kr = Kb + (size_t)(k0 + j) * DHEAD;
            d[j] = q0 * kr[lane * 2] + q1 * kr[lane * 2 + 1];
        }
#pragma unroll
        for (int j = 0; j < 4; j++) d[j] = warp_sum(d[j]) * 0.125f;
#pragma unroll
        for (int j = 0; j < 4; j++) {
            const float* vr = Vb + (size_t)(k0 + j) * DHEAD;
            v0[j] = vr[lane * 2];
            v1[j] = vr[lane * 2 + 1];
        }
#pragma unroll
        for (int j = 0; j < 4; j++) {
            float nm = fmaxf(m, d[j]);
            float c = __expf(m - nm);
            float p = __expf(d[j] - nm);
            s = s * c + p;
            a0 = a0 * c + p * v0[j];
            a1 = a1 * c + p * v1[j];
            m = nm;
        }
    }
    float inv = 1.f / s;
    upd[(size_t)gwarp * DHEAD + lane * 2]     = a0 * inv;
    upd[(size_t)gwarp * DHEAD + lane * 2 + 1] = a1 * inv;
}

// ---------------- ctx fill (broadcast vmean) ----------------
__global__ void fill_ctx_kernel(const float* __restrict__ vmean, float* __restrict__ ctx) {
    int idx = blockIdx.x * blockDim.x + threadIdx.x;
    if (idx >= M2 * HID) return;
    int c = idx & 127;
    int m = idx >> 7;
    int b = m / LSEQ;
    int h = c >> 6, d = c & 63;
    ctx[idx] = vmean[(b * NHEAD + h) * DHEAD + d];
}

// ---------------- scatter upd rows ----------------
__global__ void scatter_kernel(const float* __restrict__ upd, const int* __restrict__ Mtop,
                               float* __restrict__ ctx) {
    int idx = blockIdx.x * blockDim.x + threadIdx.x;
    if (idx >= BHCNT * UTOP * DHEAD) return;
    int d = idx & 63;
    int r = idx >> 6;
    int bh = r / UTOP;
    int b = bh / NHEAD, h = bh % NHEAD;
    int l = Mtop[r];
    ctx[((size_t)(b * LSEQ + l)) * HID + h * DHEAD + d] = upd[idx];
}

// ---------------- launch ----------------
extern "C" void kernel_launch(void* const* d_in, const int* in_sizes, int n_in,
                              void* d_out, int out_size) {
    const float* x       = (const float*)d_in[0];
    const float* conv1_w = (const float*)d_in[1];
    const float* conv1_b = (const float*)d_in[2];
    const float* conv2_w = (const float*)d_in[3];
    const float* conv2_b = (const float*)d_in[4];
    const float* wq = (const float*)d_in[5];
    const float* bq = (const float*)d_in[6];
    const float* wk = (const float*)d_in[7];
    const float* bk = (const float*)d_in[8];
    const float* wv = (const float*)d_in[9];
    const float* bv = (const float*)d_in[10];
    const float* wo = (const float*)d_in[11];
    const float* bo = (const float*)d_in[12];
    const int* index_sample = (const int*)d_in[13];
    float* out = (float*)d_out;

    float *h1, *seq, *Qp, *Kp, *Vp, *ctx, *Mv, *updv, *vmeanv, *w1t, *w2t, *part;
    int *mtop;
    cudaGetSymbolAddress((void**)&h1, g_h1);
    cudaGetSymbolAddress((void**)&seq, g_seq);
    cudaGetSymbolAddress((void**)&Qp, g_Q);
    cudaGetSymbolAddress((void**)&Kp, g_K);
    cudaGetSymbolAddress((void**)&Vp, g_V);
    cudaGetSymbolAddress((void**)&ctx, g_ctx);
    cudaGetSymbolAddress((void**)&Mv, g_M);
    cudaGetSymbolAddress((void**)&mtop, g_Mtop);
    cudaGetSymbolAddress((void**)&updv, g_upd);
    cudaGetSymbolAddress((void**)&vmeanv, g_vmean);
    cudaGetSymbolAddress((void**)&w1t, g_w1t);
    cudaGetSymbolAddress((void**)&w2t, g_w2t);
    cudaGetSymbolAddress((void**)&part, g_part);

    transpose_w_kernel<<<(HID * K1 + 255) / 256, 256>>>(conv1_w, w1t, K1);
    transpose_w_kernel<<<(HID * K2 + 255) / 256, 256>>>(conv2_w, w2t, K2);

    // conv1: im2col GEMM, split-K=2 -> reduce to h1 (NCHW, relu)
    gemm_f32x2_kernel<true, NFEAT, TLEN, SCL, H1H, H1W, 0, false, true, 128>
        <<<dim3((M1 + 127) / 128, 2), 256>>>(x, w1t, conv1_b, part, M1, K1);
    reduce_kernel<2, true, 2><<<(M1 * HID + 255) / 256, 256>>>(part, conv1_b, h1, M1);

    // conv2: im2col GEMM, split-K=4 -> reduce to seq (row-major, relu)
    gemm_f32x2_kernel<true, HID, H1H, H1W, H2H, H2W, 0, false, true, 512>
        <<<dim3((M2 + 127) / 128, 4), 256>>>(h1, w2t, conv2_b, part, M2, K2);
    reduce_kernel<4, true, 0><<<(M2 * HID + 255) / 256, 256>>>(part, conv2_b, seq, M2);

    // QKV projections (unsplit, head layout)
    gemm_f32x2_kernel<false, 0, 0, 0, 0, 0, 1, false, false, 128>
        <<<dim3((M2 + 127) / 128, 1), 256>>>(seq, wq, bq, Qp, M2, HID);
    gemm_f32x2_kernel<false, 0, 0, 0, 0, 0, 1, false, false, 128>
        <<<dim3((M2 + 127) / 128, 1), 256>>>(seq, wk, bk, Kp, M2, HID);
    gemm_f32x2_kernel<false, 0, 0, 0, 0, 0, 1, false, false, 128>
        <<<dim3((M2 + 127) / 128, 1), 256>>>(seq, wv, bv, Vp, M2, HID);

    // sampled scores -> M
    {
        int warps = BHCNT * LSEQ;
        int blocks = (warps + 3) / 4;
        sampled_m_kernel<<<blocks, 128>>>(Qp, Kp, index_sample, Mv);
    }

    topk_kernel<<<BHCNT, 256>>>(Mv, mtop);
    vmean_kernel<<<BHCNT, 64>>>(Vp, vmeanv);

    {
        int warps = BHCNT * UTOP;
        int blocks = (warps + 3) / 4;
        attn_kernel<<<blocks, 128>>>(Qp, Kp, Vp, mtop, updv);
    }

    fill_ctx_kernel<<<(M2 * HID + 255) / 256, 256>>>(vmeanv, ctx);
    scatter_kernel<<<(BHCNT * UTOP * DHEAD + 255) / 256, 256>>>(updv, mtop, ctx);

    // final projection
    gemm_f32x2_kernel<false, 0, 0, 0, 0, 0, 0, false, false, 128>
        <<<dim3((M2 + 127) / 128, 1), 256>>>(ctx, wo, bo, out, M2, HID);
}

// round 5
// speedup vs baseline: 2.0973x; 1.3649x over previous
#include <cuda_runtime.h>
#include <cstdint>
#include <math.h>

#define NEG_INF (__int_as_float(0xff800000))

// ---------------- problem constants ----------------
#define BATCH   16
#define NFEAT   16
#define TLEN    64
#define SCL     32
#define HID     128
#define FS      4
#define NHEAD   2
#define DHEAD   64

#define H1H     61
#define H1W     29
#define H2H     58
#define H2W     26
#define LSEQ    1508
#define UTOP    40

#define K1      256
#define K2      2048
#define M1      (BATCH*H1H*H1W)   // 28304
#define M2      (BATCH*LSEQ)      // 24128
#define BHCNT   (BATCH*NHEAD)     // 32

// tcgen05 available only on arch-specific (sm_103a) compilation pass
#if defined(__CUDA_ARCH_FEAT_SM103_ALL) || defined(__CUDA_ARCH_SPECIFIC__)
#define TC_PATH 1
#else
#define TC_PATH 0
#endif

// ---------------- scratch ----------------
__device__ float g_xcl[BATCH*TLEN*SCL*NFEAT];    // x channels-last
__device__ float g_h1cl[M1*HID];                 // conv1 out NHWC (row-major M1 x 128)
__device__ float g_seq[M2*HID];
__device__ float g_Q[BHCNT*LSEQ*DHEAD];
__device__ float g_K[BHCNT*LSEQ*DHEAD];
__device__ float g_V[BHCNT*LSEQ*DHEAD];
__device__ float g_ctx[M2*HID];
__device__ float g_M[BHCNT*LSEQ];
__device__ int   g_Mtop[BHCNT*UTOP];
__device__ float g_upd[BHCNT*UTOP*DHEAD];
__device__ float g_vmean[BHCNT*DHEAD];
__device__ float g_B1[HID*K1];     // conv1 weights remapped [n][s*16+ic]
__device__ float g_B2[HID*K2];     // conv2 weights remapped [n][s*128+ic]
__device__ float g_wqT[HID*HID];
__device__ float g_wkT[HID*HID];
__device__ float g_wvT[HID*HID];
__device__ float g_woT[HID*HID];

// ---------------- PTX helpers ----------------
__device__ __forceinline__ uint32_t smem_u32(const void* p) {
    uint32_t a;
    asm("{ .reg .u64 t; cvta.to.shared.u64 t, %1; cvt.u32.u64 %0, t; }" : "=r"(a) : "l"(p));
    return a;
}

#define TC_ALLOC(sa, n) \
    asm volatile("tcgen05.alloc.cta_group::1.sync.aligned.shared::cta.b32 [%0], %1;" \
                 :: "r"(sa), "r"(n) : "memory")
#define TC_DEALLOC(t, n) \
    asm volatile("tcgen05.dealloc.cta_group::1.sync.aligned.b32 %0, %1;" :: "r"(t), "r"(n))
#define TC_RELINQ() \
    asm volatile("tcgen05.relinquish_alloc_permit.cta_group::1.sync.aligned;")
#define TC_COMMIT(mb) \
    asm volatile("tcgen05.commit.cta_group::1.mbarrier::arrive::one.shared::cluster.b64 [%0];" \
                 :: "r"(mb) : "memory")
#define TC_FENCE_AFTER()  asm volatile("tcgen05.fence::after_thread_sync;" ::: "memory")
#define TC_FENCE_BEFORE() asm volatile("tcgen05.fence::before_thread_sync;" ::: "memory")
#define TC_WAIT_LD()      asm volatile("tcgen05.wait::ld.sync.aligned;" ::: "memory")
#define MB_INIT(mb, c) \
    asm volatile("mbarrier.init.shared.b64 [%0], %1;" :: "r"(mb), "r"(c) : "memory")
#define FENCE_ASYNC() asm volatile("fence.proxy.async.shared::cta;" ::: "memory")

#define MB_WAIT_PARITY(mbar_smem_addr, phase_parity) do { \
    uint32_t _mbar = (uint32_t)(mbar_smem_addr); \
    uint32_t _parity = (uint32_t)(phase_parity); \
    uint32_t _done; \
    asm volatile( \
        "{\n\t" \
        ".reg .pred p;\n\t" \
        "mbarrier.try_wait.parity.acquire.cta.shared::cta.b64 p, [%1], %2;\n\t" \
        "selp.b32 %0, 1, 0, p;\n\t" \
        "}" \
        : "=r"(_done) : "r"(_mbar), "r"(_parity) : "memory"); \
    if (!_done) { \
        asm volatile( \
            "{\n\t" \
            ".reg .pred P1;\n\t" \
            "WAIT_LOOP_%=:\n\t" \
            "mbarrier.try_wait.parity.acquire.cta.shared::cta.b64 P1, [%0], %1, 0x989680;\n\t" \
            "@P1 bra.uni WAIT_DONE_%=;\n\t" \
            "bra.uni WAIT_LOOP_%=;\n\t" \
            "WAIT_DONE_%=:\n\t" \
            "}" \
            :: "r"(_mbar), "r"(_parity) : "memory"); \
    } \
} while(0)

#define TC_LD_X32(r, tmem_addr) \
    asm volatile( \
        "tcgen05.ld.sync.aligned.32x32b.x32.b32 " \
        "{%0, %1, %2, %3, %4, %5, %6, %7, " \
        " %8, %9, %10, %11, %12, %13, %14, %15, " \
        " %16, %17, %18, %19, %20, %21, %22, %23, " \
        " %24, %25, %26, %27, %28, %29, %30, %31}, [%32];" \
        : "=r"((r)[0]),  "=r"((r)[1]),  "=r"((r)[2]),  "=r"((r)[3]), \
          "=r"((r)[4]),  "=r"((r)[5]),  "=r"((r)[6]),  "=r"((r)[7]), \
          "=r"((r)[8]),  "=r"((r)[9]),  "=r"((r)[10]), "=r"((r)[11]), \
          "=r"((r)[12]), "=r"((r)[13]), "=r"((r)[14]), "=r"((r)[15]), \
          "=r"((r)[16]), "=r"((r)[17]), "=r"((r)[18]), "=r"((r)[19]), \
          "=r"((r)[20]), "=r"((r)[21]), "=r"((r)[22]), "=r"((r)[23]), \
          "=r"((r)[24]), "=r"((r)[25]), "=r"((r)[26]), "=r"((r)[27]), \
          "=r"((r)[28]), "=r"((r)[29]), "=r"((r)[30]), "=r"((r)[31]) \
        : "r"(tmem_addr))

#if TC_PATH
__device__ __forceinline__ void mma_tf32_ss(uint32_t d_tmem, uint64_t a_desc,
                                            uint64_t b_desc, uint32_t idesc, bool accum) {
    uint32_t en = accum ? 1u : 0u;
    asm volatile(
        "{\n\t"
        ".reg .pred p;\n\t"
        "setp.ne.u32 p, %4, 0;\n\t"
        "tcgen05.mma.cta_group::1.kind::tf32 [%0], %1, %2, %3, p;\n\t"
        "}"
        :: "r"(d_tmem), "l"(a_desc), "l"(b_desc), "r"(idesc), "r"(en)
        : "memory");
}
#endif

// SW128 SMEM descriptor: layout=2, version=1, SBO=64, LBO=1
__device__ __forceinline__ uint64_t make_desc(uint32_t addr) {
    return ((uint64_t)2 << 61) | ((uint64_t)1 << 46) | ((uint64_t)64 << 32)
         | ((uint64_t)1 << 16) | (uint64_t)((addr >> 4) & 0x3FFF);
}

__device__ __forceinline__ uint32_t swz128(uint32_t off) {
    return off ^ ((off >> 3) & 0x70);
}

__device__ __forceinline__ void split_tf32(float v, float& hi, float& lo) {
    uint32_t h;
    asm("cvt.rna.tf32.f32 %0, %1;" : "=r"(h) : "f"(v));
    hi = __uint_as_float(h);
    lo = v - hi;
}

// packed fp32 FMA (fallback path)
__device__ __forceinline__ void ffma2(float2& c, const float2 a, const float2 b) {
    unsigned long long& c64 = reinterpret_cast<unsigned long long&>(c);
    const unsigned long long& a64 = reinterpret_cast<const unsigned long long&>(a);
    const unsigned long long& b64 = reinterpret_cast<const unsigned long long&>(b);
    asm("fma.rn.f32x2 %0, %1, %2, %0;" : "+l"(c64) : "l"(a64), "l"(b64));
}

// idesc: c=F32(1@4), a=TF32(2@7), b=TF32(2@10), N=128(16@17), M=128(8@24)
#define TF32_IDESC ((1u << 4) | (2u << 7) | (2u << 10) | (16u << 17) | (8u << 24))

// ---------------- prep kernels ----------------
__global__ void transpose_x_kernel(const float* __restrict__ x, float* __restrict__ xcl) {
    int idx = blockIdx.x * blockDim.x + threadIdx.x;
    if (idx >= BATCH * NFEAT * TLEN * SCL) return;
    int w = idx % SCL;
    int h = (idx / SCL) % TLEN;
    int c = (idx / (SCL * TLEN)) % NFEAT;
    int b = idx / (SCL * TLEN * NFEAT);
    xcl[((b * TLEN + h) * SCL + w) * NFEAT + c] = x[idx];
}

// conv weight remap: B[n][s*IC+ic] = w[n][ic*16 + s]   (s = kh*4+kw)
template<int IC>
__global__ void remap_w_kernel(const float* __restrict__ w, float* __restrict__ Bo) {
    int idx = blockIdx.x * blockDim.x + threadIdx.x;
    if (idx >= HID * IC * 16) return;
    int K = IC * 16;
    int n = idx / K;
    int k = idx % K;
    int ic = k / 16, s = k % 16;
    Bo[n * K + s * IC + ic] = w[idx];
}

// linear transpose: B[n][k] = w[k][n]
__global__ void transpose_w_kernel(const float* __restrict__ w, float* __restrict__ wT) {
    int idx = blockIdx.x * blockDim.x + threadIdx.x;
    if (idx >= HID * HID) return;
    int a = idx / HID;
    int b = idx % HID;
    wT[b * HID + a] = w[idx];
}

// ---------------- unified GEMM ----------------
// C[M x 128] = A[M x K] @ B^T   (B stored [n][k]), + bias, opt relu
// MODE 0: A row-major. MODE 1: conv1 im2col (xcl NHWC, IC=16). MODE 2: conv2 im2col (h1cl, IC=128)
// LAYOUT 0: out[m*128+n].  LAYOUT 1: QKV head layout.
#define GEMM_SMEM_BYTES (131072 + 1024)

template<int MODE, int KDIM, int LAYOUT, bool RELU>
__global__ void __launch_bounds__(256, 1)
gemm_tc_kernel(const float* __restrict__ Ain, const float* __restrict__ Bw,
               const float* __restrict__ bias, float* __restrict__ out, int M) {
#if TC_PATH
    // ===================== tcgen05 3xTF32 path =====================
    extern __shared__ char dynraw[];
    __shared__ uint32_t s_tmem[1];
    __shared__ __align__(8) unsigned long long s_mbar[2];

    const int tid = threadIdx.x;
    const int wid = tid >> 5;
    const int lane = tid & 31;
    const int block_m = blockIdx.x * 128;

    uint32_t dynb32 = smem_u32(dynraw);
    uint32_t smem_base = (dynb32 + 1023u) & ~1023u;
    char* dbase = dynraw + (smem_base - dynb32);
    uint32_t mbar0 = smem_u32(&s_mbar[0]);

    if (wid == 0) {
        TC_ALLOC(smem_u32(s_tmem), 512);
    }
    if (tid == 0) {
        MB_INIT(mbar0, 1);
        MB_INIT(mbar0 + 8, 1);
    }
    __syncthreads();
    uint32_t tmem;
    asm volatile("ld.shared.b32 %0, [%1];" : "=r"(tmem) : "r"(smem_u32(s_tmem)));

    const int quad = tid & 7;
    int rowi[4];
    int abase[4];
    bool aok[4];
#pragma unroll
    for (int i = 0; i < 4; i++) {
        rowi[i] = i * 32 + (tid >> 3);
        int m = block_m + rowi[i];
        aok[i] = (m < M);
        int mc = aok[i] ? m : 0;
        if (MODE == 0) {
            abase[i] = mc * KDIM;
        } else if (MODE == 1) {
            int b = mc / (H1H * H1W);
            int r = mc % (H1H * H1W);
            int oh = r / H1W, ow = r % H1W;
            abase[i] = ((b * TLEN + oh) * SCL + ow) * NFEAT;
        } else {
            int b = mc / LSEQ;
            int r = mc % LSEQ;
            int oh = r / H2W, ow = r % H2W;
            abase[i] = ((b * H1H + oh) * H1W + ow) * HID;
        }
    }
    uint32_t swz[4];
#pragma unroll
    for (int i = 0; i < 4; i++) {
        uint32_t off = (uint32_t)rowi[i] * 128u + (uint32_t)quad * 16u;
        swz[i] = swz128(off);
    }

    const int NC = KDIM / 32;
    int ph[2] = {0, 0};

    for (int c = 0; c < NC; c++) {
        const int buf = c & 1;
        if (c >= 2) {
            MB_WAIT_PARITY(mbar0 + buf * 8, ph[buf]);
            ph[buf] ^= 1;
        }
        char* Ahi = dbase + buf * 65536;
        char* Alo = Ahi + 16384;
        char* Bhi = Ahi + 32768;
        char* Blo = Ahi + 49152;

        const int kq = c * 32 + quad * 4;
#pragma unroll
        for (int i = 0; i < 4; i++) {
            float4 v = make_float4(0.f, 0.f, 0.f, 0.f);
            if (aok[i]) {
                int addr;
                if (MODE == 0) {
                    addr = abase[i] + kq;
                } else if (MODE == 1) {
                    int s = kq >> 4, ic = kq & 15;
                    addr = abase[i] + (((s >> 2) * SCL) + (s & 3)) * NFEAT + ic;
                } else {
                    int s = kq >> 7, ic = kq & 127;
                    addr = abase[i] + (((s >> 2) * H1W) + (s & 3)) * HID + ic;
                }
                v = *reinterpret_cast<const float4*>(Ain + addr);
            }
            float4 h4, l4;
            split_tf32(v.x, h4.x, l4.x);
            split_tf32(v.y, h4.y, l4.y);
            split_tf32(v.z, h4.z, l4.z);
            split_tf32(v.w, h4.w, l4.w);
            *reinterpret_cast<float4*>(Ahi + swz[i]) = h4;
            *reinterpret_cast<float4*>(Alo + swz[i]) = l4;
        }
#pragma unroll
        for (int i = 0; i < 4; i++) {
            float4 v = *reinterpret_cast<const float4*>(Bw + rowi[i] * KDIM + kq);
            float4 h4, l4;
            split_tf32(v.x, h4.x, l4.x);
            split_tf32(v.y, h4.y, l4.y);
            split_tf32(v.z, h4.z, l4.z);
            split_tf32(v.w, h4.w, l4.w);
            *reinterpret_cast<float4*>(Bhi + swz[i]) = h4;
            *reinterpret_cast<float4*>(Blo + swz[i]) = l4;
        }
        FENCE_ASYNC();
        __syncthreads();

        if (tid == 0) {
            uint32_t sb = smem_base + buf * 65536;
            uint64_t dah = make_desc(sb);
            uint64_t dal = make_desc(sb + 16384);
            uint64_t dbh = make_desc(sb + 32768);
            uint64_t dbl = make_desc(sb + 49152);
#pragma unroll
            for (int s = 0; s < 4; s++) {
                uint64_t o = (uint64_t)(s * 2);
                mma_tf32_ss(tmem, dah + o, dbh + o, TF32_IDESC, !(c == 0 && s == 0));
                mma_tf32_ss(tmem, dah + o, dbl + o, TF32_IDESC, true);
                mma_tf32_ss(tmem, dal + o, dbh + o, TF32_IDESC, true);
            }
            TC_COMMIT(mbar0 + buf * 8);
        }
    }

    {
        const int lb = (NC - 1) & 1;
        MB_WAIT_PARITY(mbar0 + lb * 8, ph[lb]);
    }
    TC_FENCE_AFTER();
    __syncthreads();

    if (wid < 4) {
        int m = block_m + wid * 32 + lane;
#pragma unroll
        for (int cb = 0; cb < 128; cb += 32) {
            uint32_t r[32];
            TC_LD_X32(r, tmem + cb);
            TC_WAIT_LD();
            if (m < M) {
                float vals[32];
#pragma unroll
                for (int j = 0; j < 32; j++) {
                    float v = __uint_as_float(r[j]) + __ldg(&bias[cb + j]);
                    if (RELU) v = fmaxf(v, 0.f);
                    vals[j] = v;
                }
                float* po;
                if (LAYOUT == 0) {
                    po = out + (size_t)m * HID + cb;
                } else {
                    int b = m / LSEQ, l = m % LSEQ;
                    int h = cb >> 6, d0 = cb & 63;
                    po = out + ((size_t)(b * NHEAD + h) * LSEQ + l) * DHEAD + d0;
                }
#pragma unroll
                for (int j = 0; j < 8; j++) {
                    *reinterpret_cast<float4*>(po + j * 4) =
                        make_float4(vals[j * 4], vals[j * 4 + 1], vals[j * 4 + 2], vals[j * 4 + 3]);
                }
            }
        }
        TC_FENCE_BEFORE();
    }
    __syncthreads();
    if (wid == 0) {
        TC_RELINQ();
        TC_DEALLOC(tmem, 512);
    }
#else
    // ===================== FFMA2 fallback (family PTX target) =====================
    extern __shared__ char dynraw[];
    float (*As)[132] = reinterpret_cast<float(*)[132]>(dynraw);
    float (*Bs)[132] = reinterpret_cast<float(*)[132]>(dynraw + 16 * 132 * 4);

    const int tid = threadIdx.x;
    const int tx = tid & 15;
    const int ty = tid >> 4;
    const int block_m = blockIdx.x * 128;

    const int lk = tid & 15;
    const int lm = tid >> 4;
    int abase[8];
    bool aok[8];
#pragma unroll
    for (int i = 0; i < 8; i++) {
        int m = block_m + lm + i * 16;
        aok[i] = (m < M);
        int mc = aok[i] ? m : 0;
        if (MODE == 0) {
            abase[i] = mc * KDIM;
        } else if (MODE == 1) {
            int b = mc / (H1H * H1W);
            int r = mc % (H1H * H1W);
            abase[i] = ((b * TLEN + r / H1W) * SCL + (r % H1W)) * NFEAT;
        } else {
            int b = mc / LSEQ;
            int r = mc % LSEQ;
            abase[i] = ((b * H1H + r / H2W) * H1W + (r % H2W)) * HID;
        }
    }

    float2 acc[8][4];
#pragma unroll
    for (int i = 0; i < 8; i++)
#pragma unroll
        for (int j = 0; j < 4; j++) acc[i][j] = make_float2(0.f, 0.f);

    for (int kt = 0; kt < KDIM; kt += 16) {
        {
            int k = kt + lk;
            int off;
            if (MODE == 0) {
                off = k;
            } else if (MODE == 1) {
                int s = k >> 4, ic = k & 15;
                off = (((s >> 2) * SCL) + (s & 3)) * NFEAT + ic;
            } else {
                int s = k >> 7, ic = k & 127;
                off = (((s >> 2) * H1W) + (s & 3)) * HID + ic;
            }
#pragma unroll
            for (int i = 0; i < 8; i++)
                As[lk][lm + i * 16] = aok[i] ? Ain[abase[i] + off] : 0.f;
        }
#pragma unroll
        for (int i = 0; i < 8; i++) {
            int idx = tid + i * 256;
            int nl = idx & 127;
            int kl = idx >> 7;
            Bs[kl][nl] = Bw[nl * KDIM + kt + kl];
        }
        __syncthreads();
#pragma unroll
        for (int k = 0; k < 16; k++) {
            float4 a0 = *reinterpret_cast<const float4*>(&As[k][ty * 4]);
            float4 a1 = *reinterpret_cast<const float4*>(&As[k][64 + ty * 4]);
            float4 b0 = *reinterpret_cast<const float4*>(&Bs[k][tx * 4]);
            float4 b1 = *reinterpret_cast<const float4*>(&Bs[k][64 + tx * 4]);
            float am[8] = {a0.x, a0.y, a0.z, a0.w, a1.x, a1.y, a1.z, a1.w};
            float2 bb[4] = {make_float2(b0.x, b0.y), make_float2(b0.z, b0.w),
                            make_float2(b1.x, b1.y), make_float2(b1.z, b1.w)};
#pragma unroll
            for (int i = 0; i < 8; i++) {
                float2 ad = make_float2(am[i], am[i]);
#pragma unroll
                for (int j = 0; j < 4; j++) ffma2(acc[i][j], ad, bb[j]);
            }
        }
        __syncthreads();
    }

#pragma unroll
    for (int i = 0; i < 8; i++) {
        int m = block_m + ((i < 4) ? (ty * 4 + i) : (64 + ty * 4 + i - 4));
        if (m >= M) continue;
#pragma unroll
        for (int j = 0; j < 4; j++) {
            int n = (j < 2) ? (tx * 4 + 2 * j) : (64 + tx * 4 + 2 * (j - 2));
            float2 v = acc[i][j];
            v.x += bias[n];
            v.y += bias[n + 1];
            if (RELU) { v.x = fmaxf(v.x, 0.f); v.y = fmaxf(v.y, 0.f); }
            if (LAYOUT == 0) {
                *reinterpret_cast<float2*>(&out[(size_t)m * HID + n]) = v;
            } else {
                int b = m / LSEQ, l = m % LSEQ;
                int h = n >> 6, d = n & 63;
                *reinterpret_cast<float2*>(
                    &out[((size_t)(b * NHEAD + h) * LSEQ + l) * DHEAD + d]) = v;
            }
        }
    }
#endif
}

// ---------------- helpers ----------------
__device__ __forceinline__ float warp_sum(float v) {
    v += __shfl_xor_sync(0xffffffffu, v, 16);
    v += __shfl_xor_sync(0xffffffffu, v, 8);
    v += __shfl_xor_sync(0xffffffffu, v, 4);
    v += __shfl_xor_sync(0xffffffffu, v, 2);
    v += __shfl_xor_sync(0xffffffffu, v, 1);
    return v;
}

// ---------------- sampled scores -> M ----------------
__global__ void sampled_m_kernel(const float* __restrict__ Q, const float* __restrict__ K,
                                 const int* __restrict__ idxs, float* __restrict__ Mout) {
    int gwarp = (blockIdx.x * blockDim.x + threadIdx.x) >> 5;
    int lane = threadIdx.x & 31;
    if (gwarp >= BHCNT * LSEQ) return;
    int bh = gwarp / LSEQ;
    int l  = gwarp % LSEQ;
    const float* q = Q + (size_t)gwarp * DHEAD;
    float q0 = q[lane * 2], q1 = q[lane * 2 + 1];
    const float* Kb = K + (size_t)bh * LSEQ * DHEAD;
    float mx = NEG_INF, sm = 0.f;
#pragma unroll 1
    for (int u = 0; u < UTOP; u += 4) {
        float d[4];
#pragma unroll
        for (int j = 0; j < 4; j++) {
            int ki = idxs[l * UTOP + u + j];
            const float* kr = Kb + (size_t)ki * DHEAD;
            d[j] = q0 * kr[lane * 2] + q1 * kr[lane * 2 + 1];
        }
#pragma unroll
        for (int j = 0; j < 4; j++) d[j] = warp_sum(d[j]);
#pragma unroll
        for (int j = 0; j < 4; j++) { mx = fmaxf(mx, d[j]); sm += d[j]; }
    }
    if (lane == 0) Mout[gwarp] = mx - sm / (float)LSEQ;
}

// ---------------- top-40 per (b,h) ----------------
__global__ void topk_kernel(const float* __restrict__ Min, int* __restrict__ Mtop) {
    __shared__ float vals[LSEQ];
    __shared__ float rv[256];
    __shared__ int   ri[256];
    int bh = blockIdx.x;
    int tid = threadIdx.x;
    for (int j = tid; j < LSEQ; j += 256) vals[j] = Min[bh * LSEQ + j];
    __syncthreads();
    for (int it = 0; it < UTOP; it++) {
        float best = NEG_INF;
        int bi = LSEQ;
        for (int j = tid; j < LSEQ; j += 256) {
            float v = vals[j];
            if (v > best) { best = v; bi = j; }
        }
        rv[tid] = best; ri[tid] = bi;
        __syncthreads();
        for (int s = 128; s > 0; s >>= 1) {
            if (tid < s) {
                float vo = rv[tid + s]; int io = ri[tid + s];
                if (vo > rv[tid] || (vo == rv[tid] && io < ri[tid])) { rv[tid] = vo; ri[tid] = io; }
            }
            __syncthreads();
        }
        if (tid == 0) {
            Mtop[bh * UTOP + it] = ri[0];
            vals[ri[0]] = NEG_INF;
        }
        __syncthreads();
    }
}

// ---------------- V mean per (b,h) ----------------
__global__ void vmean_kernel(const float* __restrict__ V, float* __restrict__ vmean) {
    int bh = blockIdx.x;
    int d = threadIdx.x;
    const float* Vb = V + (size_t)bh * LSEQ * DHEAD;
    float s = 0.f;
    for (int l = 0; l < LSEQ; l++) s += Vb[(size_t)l * DHEAD + d];
    vmean[bh * DHEAD + d] = s / (float)LSEQ;
}

// ---------------- attention over all keys for selected queries ----------------
__global__ void attn_kernel(const float* __restrict__ Q, const float* __restrict__ K,
                            const float* __restrict__ V, const int* __restrict__ Mtop,
                            float* __restrict__ upd) {
    int gwarp = (blockIdx.x * blockDim.x + threadIdx.x) >> 5;
    int lane = threadIdx.x & 31;
    if (gwarp >= BHCNT * UTOP) return;
    int bh = gwarp / UTOP;
    int l = Mtop[gwarp];
    const float* q = Q + ((size_t)bh * LSEQ + l) * DHEAD;
    float q0 = q[lane * 2], q1 = q[lane * 2 + 1];
    const float* Kb = K + (size_t)bh * LSEQ * DHEAD;
    const float* Vb = V + (size_t)bh * LSEQ * DHEAD;
    float m = NEG_INF, s = 0.f, a0 = 0.f, a1 = 0.f;
#pragma unroll 1
    for (int k0 = 0; k0 < LSEQ; k0 += 4) {
        float d[4], v0[4], v1[4];
#pragma unroll
        for (int j = 0; j < 4; j++) {
            const float* kr = Kb + (size_t)(k0 + j) * DHEAD;
            d[j] = q0 * kr[lane * 2] + q1 * kr[lane * 2 + 1];
        }
#pragma unroll
        for (int j = 0; j < 4; j++) d[j] = warp_sum(d[j]) * 0.125f;
#pragma unroll
        for (int j = 0; j < 4; j++) {
            const float* vr = Vb + (size_t)(k0 + j) * DHEAD;
            v0[j] = vr[lane * 2];
            v1[j] = vr[lane * 2 + 1];
        }
#pragma unroll
        for (int j = 0; j < 4; j++) {
            float nm = fmaxf(m, d[j]);
            float c = __expf(m - nm);
            float p = __expf(d[j] - nm);
            s = s * c + p;
            a0 = a0 * c + p * v0[j];
            a1 = a1 * c + p * v1[j];
            m = nm;
        }
    }
    float inv = 1.f / s;
    upd[(size_t)gwarp * DHEAD + lane * 2]     = a0 * inv;
    upd[(size_t)gwarp * DHEAD + lane * 2 + 1] = a1 * inv;
}

// ---------------- ctx fill (broadcast vmean) ----------------
__global__ void fill_ctx_kernel(const float* __restrict__ vmean, float* __restrict__ ctx) {
    int idx = blockIdx.x * blockDim.x + threadIdx.x;
    if (idx >= M2 * HID) return;
    int c = idx & 127;
    int m = idx >> 7;
    int b = m / LSEQ;
    int h = c >> 6, d = c & 63;
    ctx[idx] = vmean[(b * NHEAD + h) * DHEAD + d];
}

// ---------------- scatter upd rows ----------------
__global__ void scatter_kernel(const float* __restrict__ upd, const int* __restrict__ Mtop,
                               float* __restrict__ ctx) {
    int idx = blockIdx.x * blockDim.x + threadIdx.x;
    if (idx >= BHCNT * UTOP * DHEAD) return;
    int d = idx & 63;
    int r = idx >> 6;
    int bh = r / UTOP;
    int b = bh / NHEAD, h = bh % NHEAD;
    int l = Mtop[r];
    ctx[((size_t)(b * LSEQ + l)) * HID + h * DHEAD + d] = upd[idx];
}

// ---------------- launch ----------------
extern "C" void kernel_launch(void* const* d_in, const int* in_sizes, int n_in,
                              void* d_out, int out_size) {
    const float* x       = (const float*)d_in[0];
    const float* conv1_w = (const float*)d_in[1];
    const float* conv1_b = (const float*)d_in[2];
    const float* conv2_w = (const float*)d_in[3];
    const float* conv2_b = (const float*)d_in[4];
    const float* wq = (const float*)d_in[5];
    const float* bq = (const float*)d_in[6];
    const float* wk = (const float*)d_in[7];
    const float* bk = (const float*)d_in[8];
    const float* wv = (const float*)d_in[9];
    const float* bv = (const float*)d_in[10];
    const float* wo = (const float*)d_in[11];
    const float* bo = (const float*)d_in[12];
    const int* index_sample = (const int*)d_in[13];
    float* out = (float*)d_out;

    float *xcl, *h1cl, *seq, *Qp, *Kp, *Vp, *ctx, *Mv, *updv, *vmeanv;
    float *B1, *B2, *wqT, *wkT, *wvT, *woT;
    int *mtop;
    cudaGetSymbolAddress((void**)&xcl, g_xcl);
    cudaGetSymbolAddress((void**)&h1cl, g_h1cl);
    cudaGetSymbolAddress((void**)&seq, g_seq);
    cudaGetSymbolAddress((void**)&Qp, g_Q);
    cudaGetSymbolAddress((void**)&Kp, g_K);
    cudaGetSymbolAddress((void**)&Vp, g_V);
    cudaGetSymbolAddress((void**)&ctx, g_ctx);
    cudaGetSymbolAddress((void**)&Mv, g_M);
    cudaGetSymbolAddress((void**)&mtop, g_Mtop);
    cudaGetSymbolAddress((void**)&updv, g_upd);
    cudaGetSymbolAddress((void**)&vmeanv, g_vmean);
    cudaGetSymbolAddress((void**)&B1, g_B1);
    cudaGetSymbolAddress((void**)&B2, g_B2);
    cudaGetSymbolAddress((void**)&wqT, g_wqT);
    cudaGetSymbolAddress((void**)&wkT, g_wkT);
    cudaGetSymbolAddress((void**)&wvT, g_wvT);
    cudaGetSymbolAddress((void**)&woT, g_woT);

    cudaFuncSetAttribute(gemm_tc_kernel<1, K1, 0, true>,
                         cudaFuncAttributeMaxDynamicSharedMemorySize, GEMM_SMEM_BYTES);
    cudaFuncSetAttribute(gemm_tc_kernel<2, K2, 0, true>,
                         cudaFuncAttributeMaxDynamicSharedMemorySize, GEMM_SMEM_BYTES);
    cudaFuncSetAttribute(gemm_tc_kernel<0, HID, 1, false>,
                         cudaFuncAttributeMaxDynamicSharedMemorySize, GEMM_SMEM_BYTES);
    cudaFuncSetAttribute(gemm_tc_kernel<0, HID, 0, false>,
                         cudaFuncAttributeMaxDynamicSharedMemorySize, GEMM_SMEM_BYTES);

    // prep
    transpose_x_kernel<<<(BATCH * NFEAT * TLEN * SCL + 255) / 256, 256>>>(x, xcl);
    remap_w_kernel<NFEAT><<<(HID * K1 + 255) / 256, 256>>>(conv1_w, B1);
    remap_w_kernel<HID><<<(HID * K2 + 255) / 256, 256>>>(conv2_w, B2);
    transpose_w_kernel<<<(HID * HID + 255) / 256, 256>>>(wq, wqT);
    transpose_w_kernel<<<(HID * HID + 255) / 256, 256>>>(wk, wkT);
    transpose_w_kernel<<<(HID * HID + 255) / 256, 256>>>(wv, wvT);
    transpose_w_kernel<<<(HID * HID + 255) / 256, 256>>>(wo, woT);

    // conv1 -> h1cl (NHWC row-major), relu
    gemm_tc_kernel<1, K1, 0, true>
        <<<(M1 + 127) / 128, 256, GEMM_SMEM_BYTES>>>(xcl, B1, conv1_b, h1cl, M1);

    // conv2 -> seq (row-major), relu
    gemm_tc_kernel<2, K2, 0, true>
        <<<(M2 + 127) / 128, 256, GEMM_SMEM_BYTES>>>(h1cl, B2, conv2_b, seq, M2);

    // QKV projections (head layout)
    gemm_tc_kernel<0, HID, 1, false>
        <<<(M2 + 127) / 128, 256, GEMM_SMEM_BYTES>>>(seq, wqT, bq, Qp, M2);
    gemm_tc_kernel<0, HID, 1, false>
        <<<(M2 + 127) / 128, 256, GEMM_SMEM_BYTES>>>(seq, wkT, bk, Kp, M2);
    gemm_tc_kernel<0, HID, 1, false>
        <<<(M2 + 127) / 128, 256, GEMM_SMEM_BYTES>>>(seq, wvT, bv, Vp, M2);

    // sampled scores -> M
    {
        int warps = BHCNT * LSEQ;
        int blocks = (warps + 3) / 4;
        sampled_m_kernel<<<blocks, 128>>>(Qp, Kp, index_sample, Mv);
    }

    topk_kernel<<<BHCNT, 256>>>(Mv, mtop);
    vmean_kernel<<<BHCNT, 64>>>(Vp, vmeanv);

    {
        int warps = BHCNT * UTOP;
        int blocks = (warps + 3) / 4;
        attn_kernel<<<blocks, 128>>>(Qp, Kp, Vp, mtop, updv);
    }

    fill_ctx_kernel<<<(M2 * HID + 255) / 256, 256>>>(vmeanv, ctx);
    scatter_kernel<<<(BHCNT * UTOP * DHEAD + 255) / 256, 256>>>(updv, mtop, ctx);

    // final projection
    gemm_tc_kernel<0, HID, 0, false>
        <<<(M2 + 127) / 128, 256, GEMM_SMEM_BYTES>>>(ctx, woT, bo, out, M2);
}

// round 6
// speedup vs baseline: 2.8957x; 1.3807x over previous
#include <cuda_runtime.h>
#include <cstdint>
#include <math.h>

#define NEG_INF (__int_as_float(0xff800000))

// ---------------- problem constants ----------------
#define BATCH   16
#define NFEAT   16
#define TLEN    64
#define SCL     32
#define HID     128
#define FS      4
#define NHEAD   2
#define DHEAD   64

#define H1H     61
#define H1W     29
#define H2H     58
#define H2W     26
#define LSEQ    1508
#define UTOP    40

#define K1      256
#define K2      2048
#define M1      (BATCH*H1H*H1W)   // 28304
#define M2      (BATCH*LSEQ)      // 24128
#define BHCNT   (BATCH*NHEAD)     // 32

#if defined(__CUDA_ARCH_FEAT_SM103_ALL) || defined(__CUDA_ARCH_SPECIFIC__)
#define TC_PATH 1
#else
#define TC_PATH 0
#endif

// ---------------- scratch ----------------
__device__ float g_xcl[BATCH*TLEN*SCL*NFEAT];
__device__ float g_h1cl[M1*HID];
__device__ float g_seq[M2*HID];
__device__ float g_Q[BHCNT*LSEQ*DHEAD];
__device__ float g_K[BHCNT*LSEQ*DHEAD];
__device__ float g_V[BHCNT*LSEQ*DHEAD];
__device__ float g_ctx[M2*HID];
__device__ float g_M[BHCNT*LSEQ];
__device__ int   g_Mtop[BHCNT*UTOP];
__device__ float g_upd[BHCNT*UTOP*DHEAD];
__device__ float g_vmean[BHCNT*DHEAD];
__device__ float g_B1[HID*K1];
__device__ float g_B2[HID*K2];
__device__ float g_wqkvT[3*HID*HID];
__device__ float g_woT[HID*HID];

// ---------------- PTX helpers ----------------
__device__ __forceinline__ uint32_t smem_u32(const void* p) {
    uint32_t a;
    asm("{ .reg .u64 t; cvta.to.shared.u64 t, %1; cvt.u32.u64 %0, t; }" : "=r"(a) : "l"(p));
    return a;
}

#define TC_ALLOC(sa, n) \
    asm volatile("tcgen05.alloc.cta_group::1.sync.aligned.shared::cta.b32 [%0], %1;" \
                 :: "r"(sa), "r"(n) : "memory")
#define TC_DEALLOC(t, n) \
    asm volatile("tcgen05.dealloc.cta_group::1.sync.aligned.b32 %0, %1;" :: "r"(t), "r"(n))
#define TC_RELINQ() \
    asm volatile("tcgen05.relinquish_alloc_permit.cta_group::1.sync.aligned;")
#define TC_COMMIT(mb) \
    asm volatile("tcgen05.commit.cta_group::1.mbarrier::arrive::one.shared::cluster.b64 [%0];" \
                 :: "r"(mb) : "memory")
#define TC_FENCE_AFTER()  asm volatile("tcgen05.fence::after_thread_sync;" ::: "memory")
#define TC_FENCE_BEFORE() asm volatile("tcgen05.fence::before_thread_sync;" ::: "memory")
#define TC_WAIT_LD()      asm volatile("tcgen05.wait::ld.sync.aligned;" ::: "memory")
#define MB_INIT(mb, c) \
    asm volatile("mbarrier.init.shared.b64 [%0], %1;" :: "r"(mb), "r"(c) : "memory")
#define FENCE_ASYNC() asm volatile("fence.proxy.async.shared::cta;" ::: "memory")

#define MB_WAIT_PARITY(mbar_smem_addr, phase_parity) do { \
    uint32_t _mbar = (uint32_t)(mbar_smem_addr); \
    uint32_t _parity = (uint32_t)(phase_parity); \
    uint32_t _done; \
    asm volatile( \
        "{\n\t" \
        ".reg .pred p;\n\t" \
        "mbarrier.try_wait.parity.acquire.cta.shared::cta.b64 p, [%1], %2;\n\t" \
        "selp.b32 %0, 1, 0, p;\n\t" \
        "}" \
        : "=r"(_done) : "r"(_mbar), "r"(_parity) : "memory"); \
    if (!_done) { \
        asm volatile( \
            "{\n\t" \
            ".reg .pred P1;\n\t" \
            "WAIT_LOOP_%=:\n\t" \
            "mbarrier.try_wait.parity.acquire.cta.shared::cta.b64 P1, [%0], %1, 0x989680;\n\t" \
            "@P1 bra.uni WAIT_DONE_%=;\n\t" \
            "bra.uni WAIT_LOOP_%=;\n\t" \
            "WAIT_DONE_%=:\n\t" \
            "}" \
            :: "r"(_mbar), "r"(_parity) : "memory"); \
    } \
} while(0)

#define TC_LD_X32(r, tmem_addr) \
    asm volatile( \
        "tcgen05.ld.sync.aligned.32x32b.x32.b32 " \
        "{%0, %1, %2, %3, %4, %5, %6, %7, " \
        " %8, %9, %10, %11, %12, %13, %14, %15, " \
        " %16, %17, %18, %19, %20, %21, %22, %23, " \
        " %24, %25, %26, %27, %28, %29, %30, %31}, [%32];" \
        : "=r"((r)[0]),  "=r"((r)[1]),  "=r"((r)[2]),  "=r"((r)[3]), \
          "=r"((r)[4]),  "=r"((r)[5]),  "=r"((r)[6]),  "=r"((r)[7]), \
          "=r"((r)[8]),  "=r"((r)[9]),  "=r"((r)[10]), "=r"((r)[11]), \
          "=r"((r)[12]), "=r"((r)[13]), "=r"((r)[14]), "=r"((r)[15]), \
          "=r"((r)[16]), "=r"((r)[17]), "=r"((r)[18]), "=r"((r)[19]), \
          "=r"((r)[20]), "=r"((r)[21]), "=r"((r)[22]), "=r"((r)[23]), \
          "=r"((r)[24]), "=r"((r)[25]), "=r"((r)[26]), "=r"((r)[27]), \
          "=r"((r)[28]), "=r"((r)[29]), "=r"((r)[30]), "=r"((r)[31]) \
        : "r"(tmem_addr))

#if TC_PATH
__device__ __forceinline__ void mma_tf32_ss(uint32_t d_tmem, uint64_t a_desc,
                                            uint64_t b_desc, uint32_t idesc, bool accum) {
    uint32_t en = accum ? 1u : 0u;
    asm volatile(
        "{\n\t"
        ".reg .pred p;\n\t"
        "setp.ne.u32 p, %4, 0;\n\t"
        "tcgen05.mma.cta_group::1.kind::tf32 [%0], %1, %2, %3, p;\n\t"
        "}"
        :: "r"(d_tmem), "l"(a_desc), "l"(b_desc), "r"(idesc), "r"(en)
        : "memory");
}
#endif

__device__ __forceinline__ uint64_t make_desc(uint32_t addr) {
    return ((uint64_t)2 << 61) | ((uint64_t)1 << 46) | ((uint64_t)64 << 32)
         | ((uint64_t)1 << 16) | (uint64_t)((addr >> 4) & 0x3FFF);
}

__device__ __forceinline__ uint32_t swz128(uint32_t off) {
    return off ^ ((off >> 3) & 0x70);
}

__device__ __forceinline__ void split_tf32(float v, float& hi, float& lo) {
    uint32_t h;
    asm("cvt.rna.tf32.f32 %0, %1;" : "=r"(h) : "f"(v));
    hi = __uint_as_float(h);
    lo = v - hi;
}

// idesc: c=F32(1@4), a=TF32(2@7), b=TF32(2@10), N=128(16@17), M=128(8@24)
#define TF32_IDESC ((1u << 4) | (2u << 7) | (2u << 10) | (16u << 17) | (8u << 24))

// ---------------- fused prep kernel ----------------
// segments: xcl | B1 remap | B2 remap | wqkvT | woT
#define PREP_S0 (BATCH*NFEAT*TLEN*SCL)          // 524288
#define PREP_S1 (PREP_S0 + HID*K1)              // +32768
#define PREP_S2 (PREP_S1 + HID*K2)              // +262144
#define PREP_S3 (PREP_S2 + 3*HID*HID)           // +49152
#define PREP_S4 (PREP_S3 + HID*HID)             // +16384
__global__ void prep_kernel(const float* __restrict__ x,
                            const float* __restrict__ c1w, const float* __restrict__ c2w,
                            const float* __restrict__ wq, const float* __restrict__ wk,
                            const float* __restrict__ wv, const float* __restrict__ wo,
                            float* __restrict__ xcl, float* __restrict__ B1,
                            float* __restrict__ B2, float* __restrict__ wqkvT,
                            float* __restrict__ woT) {
    int idx = blockIdx.x * blockDim.x + threadIdx.x;
    if (idx < PREP_S0) {
        int w = idx % SCL;
        int h = (idx / SCL) % TLEN;
        int c = (idx / (SCL * TLEN)) % NFEAT;
        int b = idx / (SCL * TLEN * NFEAT);
        xcl[((b * TLEN + h) * SCL + w) * NFEAT + c] = x[idx];
    } else if (idx < PREP_S1) {
        int i = idx - PREP_S0;
        int n = i / K1, k = i % K1;
        int ic = k / 16, s = k % 16;
        B1[n * K1 + s * NFEAT + ic] = c1w[i];
    } else if (idx < PREP_S2) {
        int i = idx - PREP_S1;
        int n = i / K2, k = i % K2;
        int ic = k / 16, s = k % 16;
        B2[n * K2 + s * HID + ic] = c2w[i];
    } else if (idx < PREP_S3) {
        int i = idx - PREP_S2;
        int mat = i / (HID * HID);
        int r = i % (HID * HID);
        int a = r / HID, b = r % HID;   // source w[a][b]
        const float* w = (mat == 0) ? wq : (mat == 1) ? wk : wv;
        wqkvT[mat * HID * HID + b * HID + a] = w[r];
    } else if (idx < PREP_S4) {
        int i = idx - PREP_S3;
        int a = i / HID, b = i % HID;
        woT[b * HID + a] = wo[i];
    }
}

// ---------------- generic tcgen05 3xTF32 GEMM (double-buffered, reg prefetch) ---
// MODE 0: A row-major. MODE 1: conv1 im2col (NHWC, IC=16). MODE 2: conv2 im2col (IC=128)
#define GEMM_SMEM_BYTES (131072 + 1024)

template<int MODE, int KDIM, bool RELU>
__global__ void __launch_bounds__(256, 1)
gemm_tc_kernel(const float* __restrict__ Ain, const float* __restrict__ Bw,
               const float* __restrict__ bias, float* __restrict__ out, int M) {
#if TC_PATH
    extern __shared__ char dynraw[];
    __shared__ uint32_t s_tmem[1];
    __shared__ __align__(8) unsigned long long s_mbar[2];

    const int tid = threadIdx.x;
    const int wid = tid >> 5;
    const int lane = tid & 31;
    const int block_m = blockIdx.x * 128;

    uint32_t dynb32 = smem_u32(dynraw);
    uint32_t smem_base = (dynb32 + 1023u) & ~1023u;
    char* dbase = dynraw + (smem_base - dynb32);
    uint32_t mbar0 = smem_u32(&s_mbar[0]);

    if (wid == 0) TC_ALLOC(smem_u32(s_tmem), 512);
    if (tid == 0) { MB_INIT(mbar0, 1); MB_INIT(mbar0 + 8, 1); }
    __syncthreads();
    uint32_t tmem;
    asm volatile("ld.shared.b32 %0, [%1];" : "=r"(tmem) : "r"(smem_u32(s_tmem)));

    const int quad = tid & 7;
    int rowi[4], abase[4];
    bool aok[4];
#pragma unroll
    for (int i = 0; i < 4; i++) {
        rowi[i] = i * 32 + (tid >> 3);
        int m = block_m + rowi[i];
        aok[i] = (m < M);
        int mc = aok[i] ? m : 0;
        if (MODE == 0) {
            abase[i] = mc * KDIM;
        } else if (MODE == 1) {
            int b = mc / (H1H * H1W);
            int r = mc % (H1H * H1W);
            abase[i] = ((b * TLEN + r / H1W) * SCL + (r % H1W)) * NFEAT;
        } else {
            int b = mc / LSEQ;
            int r = mc % LSEQ;
            abase[i] = ((b * H1H + r / H2W) * H1W + (r % H2W)) * HID;
        }
    }
    uint32_t swz[4];
#pragma unroll
    for (int i = 0; i < 4; i++)
        swz[i] = swz128((uint32_t)rowi[i] * 128u + (uint32_t)quad * 16u);

    float4 areg[4], breg[4];
    auto load_regs = [&](int c) {
        const int kq = c * 32 + quad * 4;
#pragma unroll
        for (int i = 0; i < 4; i++) {
            areg[i] = make_float4(0.f, 0.f, 0.f, 0.f);
            if (aok[i]) {
                int addr;
                if (MODE == 0) {
                    addr = abase[i] + kq;
                } else if (MODE == 1) {
                    int s = kq >> 4, ic = kq & 15;
                    addr = abase[i] + (((s >> 2) * SCL) + (s & 3)) * NFEAT + ic;
                } else {
                    int s = kq >> 7, ic = kq & 127;
                    addr = abase[i] + (((s >> 2) * H1W) + (s & 3)) * HID + ic;
                }
                areg[i] = *reinterpret_cast<const float4*>(Ain + addr);
            }
            breg[i] = *reinterpret_cast<const float4*>(Bw + rowi[i] * KDIM + kq);
        }
    };
    auto store_tiles = [&](int buf) {
        char* Ahi = dbase + buf * 65536;
        char* Alo = Ahi + 16384;
        char* Bhi = Ahi + 32768;
        char* Blo = Ahi + 49152;
#pragma unroll
        for (int i = 0; i < 4; i++) {
            float4 h4, l4;
            split_tf32(areg[i].x, h4.x, l4.x);
            split_tf32(areg[i].y, h4.y, l4.y);
            split_tf32(areg[i].z, h4.z, l4.z);
            split_tf32(areg[i].w, h4.w, l4.w);
            *reinterpret_cast<float4*>(Ahi + swz[i]) = h4;
            *reinterpret_cast<float4*>(Alo + swz[i]) = l4;
            split_tf32(breg[i].x, h4.x, l4.x);
            split_tf32(breg[i].y, h4.y, l4.y);
            split_tf32(breg[i].z, h4.z, l4.z);
            split_tf32(breg[i].w, h4.w, l4.w);
            *reinterpret_cast<float4*>(Bhi + swz[i]) = h4;
            *reinterpret_cast<float4*>(Blo + swz[i]) = l4;
        }
    };

    const int NC = KDIM / 32;
    int ph[2] = {0, 0};
    load_regs(0);

    for (int c = 0; c < NC; c++) {
        const int buf = c & 1;
        if (c >= 2) {
            MB_WAIT_PARITY(mbar0 + buf * 8, ph[buf]);
            ph[buf] ^= 1;
        }
        store_tiles(buf);
        if (c + 1 < NC) load_regs(c + 1);   // prefetch: LDG latency hidden behind fence/sync/MMA
        FENCE_ASYNC();
        __syncthreads();
        if (tid == 0) {
            uint32_t sb = smem_base + buf * 65536;
            uint64_t dah = make_desc(sb);
            uint64_t dal = make_desc(sb + 16384);
            uint64_t dbh = make_desc(sb + 32768);
            uint64_t dbl = make_desc(sb + 49152);
#pragma unroll
            for (int s = 0; s < 4; s++) {
                uint64_t o = (uint64_t)(s * 2);
                mma_tf32_ss(tmem, dah + o, dbh + o, TF32_IDESC, !(c == 0 && s == 0));
                mma_tf32_ss(tmem, dah + o, dbl + o, TF32_IDESC, true);
                mma_tf32_ss(tmem, dal + o, dbh + o, TF32_IDESC, true);
            }
            TC_COMMIT(mbar0 + buf * 8);
        }
    }
    {
        const int lb = (NC - 1) & 1;
        MB_WAIT_PARITY(mbar0 + lb * 8, ph[lb]);
    }
    TC_FENCE_AFTER();
    __syncthreads();

    if (wid < 4) {
        int m = block_m + wid * 32 + lane;
#pragma unroll
        for (int cb = 0; cb < 128; cb += 32) {
            uint32_t r[32];
            TC_LD_X32(r, tmem + cb);
            TC_WAIT_LD();
            if (m < M) {
                float* po = out + (size_t)m * HID + cb;
#pragma unroll
                for (int j = 0; j < 8; j++) {
                    float4 v;
                    v.x = __uint_as_float(r[j * 4 + 0]) + __ldg(&bias[cb + j * 4 + 0]);
                    v.y = __uint_as_float(r[j * 4 + 1]) + __ldg(&bias[cb + j * 4 + 1]);
                    v.z = __uint_as_float(r[j * 4 + 2]) + __ldg(&bias[cb + j * 4 + 2]);
                    v.w = __uint_as_float(r[j * 4 + 3]) + __ldg(&bias[cb + j * 4 + 3]);
                    if (RELU) {
                        v.x = fmaxf(v.x, 0.f); v.y = fmaxf(v.y, 0.f);
                        v.z = fmaxf(v.z, 0.f); v.w = fmaxf(v.w, 0.f);
                    }
                    *reinterpret_cast<float4*>(po + j * 4) = v;
                }
            }
        }
        TC_FENCE_BEFORE();
    }
    __syncthreads();
    if (wid == 0) { TC_RELINQ(); TC_DEALLOC(tmem, 512); }
#else
    // naive fallback (family PTX pass only; never selected on GB300 — exact sm_103a cubin wins)
    const int tid = threadIdx.x;
    const int block_m = blockIdx.x * 128;
    for (int e = tid; e < 128 * 128; e += 256) {
        int mi = e >> 7, n = e & 127;
        int m = block_m + mi;
        if (m >= M) continue;
        float acc = 0.f;
        for (int k = 0; k < KDIM; k++) {
            float a;
            if (MODE == 0) {
                a = Ain[(size_t)m * KDIM + k];
            } else if (MODE == 1) {
                int b = m / (H1H * H1W), r = m % (H1H * H1W);
                int s = k >> 4, ic = k & 15;
                a = Ain[((b * TLEN + r / H1W + (s >> 2)) * SCL + (r % H1W) + (s & 3)) * NFEAT + ic];
            } else {
                int b = m / LSEQ, r = m % LSEQ;
                int s = k >> 7, ic = k & 127;
                a = Ain[((b * H1H + r / H2W + (s >> 2)) * H1W + (r % H2W) + (s & 3)) * HID + ic];
            }
            acc += a * Bw[n * KDIM + k];
        }
        acc += bias[n];
        if (RELU) acc = fmaxf(acc, 0.f);
        out[(size_t)m * HID + n] = acc;
    }
#endif
}

// ---------------- fused QKV GEMM (single-buffered, 3 weight mats) ----------------
template<int DUMMY>
__global__ void __launch_bounds__(256, 1)
gemm_qkv_kernel(const float* __restrict__ Ain, const float* __restrict__ Bw,
                const float* __restrict__ bq, const float* __restrict__ bk,
                const float* __restrict__ bv,
                float* __restrict__ Qo, float* __restrict__ Ko, float* __restrict__ Vo,
                int M) {
#if TC_PATH
    extern __shared__ char dynraw[];
    __shared__ uint32_t s_tmem[1];
    __shared__ __align__(8) unsigned long long s_mbar[1];

    const int tid = threadIdx.x;
    const int wid = tid >> 5;
    const int lane = tid & 31;
    const int block_m = blockIdx.x * 128;

    uint32_t dynb32 = smem_u32(dynraw);
    uint32_t smem_base = (dynb32 + 1023u) & ~1023u;
    char* dbase = dynraw + (smem_base - dynb32);
    uint32_t mbar0 = smem_u32(&s_mbar[0]);

    if (wid == 0) TC_ALLOC(smem_u32(s_tmem), 512);
    if (tid == 0) MB_INIT(mbar0, 1);
    __syncthreads();
    uint32_t tmem;
    asm volatile("ld.shared.b32 %0, [%1];" : "=r"(tmem) : "r"(smem_u32(s_tmem)));

    const int quad = tid & 7;
    int rowi[4];
#pragma unroll
    for (int i = 0; i < 4; i++) rowi[i] = i * 32 + (tid >> 3);
    uint32_t swz[4];
#pragma unroll
    for (int i = 0; i < 4; i++)
        swz[i] = swz128((uint32_t)rowi[i] * 128u + (uint32_t)quad * 16u);
    bool aok[4];
#pragma unroll
    for (int i = 0; i < 4; i++) aok[i] = (block_m + rowi[i] < M);

    // smem: Ahi | Alo | B0hi | B0lo | B1hi | B1lo | B2hi | B2lo  (16K each)
    const int NC = HID / 32;   // 4
    int ph = 0;
    for (int c = 0; c < NC; c++) {
        if (c > 0) { MB_WAIT_PARITY(mbar0, ph); ph ^= 1; }
        const int kq = c * 32 + quad * 4;
        // A tile
#pragma unroll
        for (int i = 0; i < 4; i++) {
            float4 v = make_float4(0.f, 0.f, 0.f, 0.f);
            if (aok[i]) v = *reinterpret_cast<const float4*>(Ain + (size_t)(block_m + rowi[i]) * HID + kq);
            float4 h4, l4;
            split_tf32(v.x, h4.x, l4.x);
            split_tf32(v.y, h4.y, l4.y);
            split_tf32(v.z, h4.z, l4.z);
            split_tf32(v.w, h4.w, l4.w);
            *reinterpret_cast<float4*>(dbase + swz[i]) = h4;
            *reinterpret_cast<float4*>(dbase + 16384 + swz[i]) = l4;
        }
        // 3 B tiles
#pragma unroll
        for (int mat = 0; mat < 3; mat++) {
            char* Bhi = dbase + 32768 + mat * 32768;
            char* Blo = Bhi + 16384;
#pragma unroll
            for (int i = 0; i < 4; i++) {
                float4 v = *reinterpret_cast<const float4*>(Bw + mat * HID * HID + rowi[i] * HID + kq);
                float4 h4, l4;
                split_tf32(v.x, h4.x, l4.x);
                split_tf32(v.y, h4.y, l4.y);
                split_tf32(v.z, h4.z, l4.z);
                split_tf32(v.w, h4.w, l4.w);
                *reinterpret_cast<float4*>(Bhi + swz[i]) = h4;
                *reinterpret_cast<float4*>(Blo + swz[i]) = l4;
            }
        }
        FENCE_ASYNC();
        __syncthreads();
        if (tid == 0) {
            uint64_t dah = make_desc(smem_base);
            uint64_t dal = make_desc(smem_base + 16384);
#pragma unroll
            for (int mat = 0; mat < 3; mat++) {
                uint64_t dbh = make_desc(smem_base + 32768 + mat * 32768);
                uint64_t dbl = make_desc(smem_base + 49152 + mat * 32768);
                uint32_t dtm = tmem + mat * 128;
#pragma unroll
                for (int s = 0; s < 4; s++) {
                    uint64_t o = (uint64_t)(s * 2);
                    mma_tf32_ss(dtm, dah + o, dbh + o, TF32_IDESC, !(c == 0 && s == 0));
                    mma_tf32_ss(dtm, dah + o, dbl + o, TF32_IDESC, true);
                    mma_tf32_ss(dtm, dal + o, dbh + o, TF32_IDESC, true);
                }
            }
            TC_COMMIT(mbar0);
        }
        // all threads must not overwrite smem until MMAs done -> wait at loop top
        __syncthreads();
    }
    MB_WAIT_PARITY(mbar0, ph);
    TC_FENCE_AFTER();
    __syncthreads();

    if (wid < 4) {
        int m = block_m + wid * 32 + lane;
        int b = 0, l = 0;
        if (m < M) { b = m / LSEQ; l = m % LSEQ; }
#pragma unroll
        for (int mat = 0; mat < 3; mat++) {
            const float* bias = (mat == 0) ? bq : (mat == 1) ? bk : bv;
            float* outp = (mat == 0) ? Qo : (mat == 1) ? Ko : Vo;
#pragma unroll
            for (int cb = 0; cb < 128; cb += 32) {
                uint32_t r[32];
                TC_LD_X32(r, tmem + mat * 128 + cb);
                TC_WAIT_LD();
                if (m < M) {
                    int h = cb >> 6, d0 = cb & 63;
                    float* po = outp + ((size_t)(b * NHEAD + h) * LSEQ + l) * DHEAD + d0;
#pragma unroll
                    for (int j = 0; j < 8; j++) {
                        float4 v;
                        v.x = __uint_as_float(r[j * 4 + 0]) + __ldg(&bias[cb + j * 4 + 0]);
                        v.y = __uint_as_float(r[j * 4 + 1]) + __ldg(&bias[cb + j * 4 + 1]);
                        v.z = __uint_as_float(r[j * 4 + 2]) + __ldg(&bias[cb + j * 4 + 2]);
                        v.w = __uint_as_float(r[j * 4 + 3]) + __ldg(&bias[cb + j * 4 + 3]);
                        *reinterpret_cast<float4*>(po + j * 4) = v;
                    }
                }
            }
        }
        TC_FENCE_BEFORE();
    }
    __syncthreads();
    if (wid == 0) { TC_RELINQ(); TC_DEALLOC(tmem, 512); }
#else
    const int tid = threadIdx.x;
    const int block_m = blockIdx.x * 128;
    for (int e = tid; e < 128 * 128 * 3; e += 256) {
        int mat = e / (128 * 128);
        int r = e % (128 * 128);
        int mi = r >> 7, n = r & 127;
        int m = block_m + mi;
        if (m >= M) continue;
        float acc = 0.f;
        for (int k = 0; k < HID; k++)
            acc += Ain[(size_t)m * HID + k] * Bw[mat * HID * HID + n * HID + k];
        const float* bias = (mat == 0) ? bq : (mat == 1) ? bk : bv;
        float* outp = (mat == 0) ? Qo : (mat == 1) ? Ko : Vo;
        acc += bias[n];
        int b = m / LSEQ, l = m % LSEQ;
        int h = n >> 6, d = n & 63;
        outp[((size_t)(b * NHEAD + h) * LSEQ + l) * DHEAD + d] = acc;
    }
#endif
}

// ---------------- helpers ----------------
__device__ __forceinline__ float warp_sum(float v) {
    v += __shfl_xor_sync(0xffffffffu, v, 16);
    v += __shfl_xor_sync(0xffffffffu, v, 8);
    v += __shfl_xor_sync(0xffffffffu, v, 4);
    v += __shfl_xor_sync(0xffffffffu, v, 2);
    v += __shfl_xor_sync(0xffffffffu, v, 1);
    return v;
}

// ---------------- sampled scores -> M ----------------
__global__ void sampled_m_kernel(const float* __restrict__ Q, const float* __restrict__ K,
                                 const int* __restrict__ idxs, float* __restrict__ Mout) {
    int gwarp = (blockIdx.x * blockDim.x + threadIdx.x) >> 5;
    int lane = threadIdx.x & 31;
    if (gwarp >= BHCNT * LSEQ) return;
    int bh = gwarp / LSEQ;
    int l  = gwarp % LSEQ;
    const float* q = Q + (size_t)gwarp * DHEAD;
    float q0 = q[lane * 2], q1 = q[lane * 2 + 1];
    const float* Kb = K + (size_t)bh * LSEQ * DHEAD;
    float mx = NEG_INF, sm = 0.f;
#pragma unroll 1
    for (int u = 0; u < UTOP; u += 4) {
        float d[4];
#pragma unroll
        for (int j = 0; j < 4; j++) {
            int ki = idxs[l * UTOP + u + j];
            const float* kr = Kb + (size_t)ki * DHEAD;
            d[j] = q0 * kr[lane * 2] + q1 * kr[lane * 2 + 1];
        }
#pragma unroll
        for (int j = 0; j < 4; j++) d[j] = warp_sum(d[j]);
#pragma unroll
        for (int j = 0; j < 4; j++) { mx = fmaxf(mx, d[j]); sm += d[j]; }
    }
    if (lane == 0) Mout[gwarp] = mx - sm / (float)LSEQ;
}

// ---------------- top-40 per (b,h) ----------------
__global__ void topk_kernel(const float* __restrict__ Min, int* __restrict__ Mtop) {
    __shared__ float vals[LSEQ];
    __shared__ float rv[256];
    __shared__ int   ri[256];
    int bh = blockIdx.x;
    int tid = threadIdx.x;
    for (int j = tid; j < LSEQ; j += 256) vals[j] = Min[bh * LSEQ + j];
    __syncthreads();
    for (int it = 0; it < UTOP; it++) {
        float best = NEG_INF;
        int bi = LSEQ;
        for (int j = tid; j < LSEQ; j += 256) {
            float v = vals[j];
            if (v > best) { best = v; bi = j; }
        }
        rv[tid] = best; ri[tid] = bi;
        __syncthreads();
        for (int s = 128; s > 0; s >>= 1) {
            if (tid < s) {
                float vo = rv[tid + s]; int io = ri[tid + s];
                if (vo > rv[tid] || (vo == rv[tid] && io < ri[tid])) { rv[tid] = vo; ri[tid] = io; }
            }
            __syncthreads();
        }
        if (tid == 0) {
            Mtop[bh * UTOP + it] = ri[0];
            vals[ri[0]] = NEG_INF;
        }
        __syncthreads();
    }
}

// ---------------- V mean per (b,h) (parallel) ----------------
#define VSLICE 377    // LSEQ/4
__global__ void vmean_kernel(const float* __restrict__ V, float* __restrict__ vmean) {
    __shared__ float part[4][DHEAD];
    int bh = blockIdx.x;
    int tid = threadIdx.x;            // 256
    int d = tid & 63;
    int sl = tid >> 6;                // 0..3
    const float* Vb = V + (size_t)bh * LSEQ * DHEAD;
    float s = 0.f;
    int beg = sl * VSLICE, end = beg + VSLICE;
    for (int l = beg; l < end; l++) s += Vb[(size_t)l * DHEAD + d];
    part[sl][d] = s;
    __syncthreads();
    if (tid < DHEAD)
        vmean[bh * DHEAD + tid] =
            (part[0][tid] + part[1][tid] + part[2][tid] + part[3][tid]) / (float)LSEQ;
}

// ---------------- attention: 1 block (4 warps) per selected query ----------------
__global__ void attn_kernel(const float* __restrict__ Q, const float* __restrict__ K,
                            const float* __restrict__ V, const int* __restrict__ Mtop,
                            float* __restrict__ upd) {
    __shared__ float s_m[4], s_s[4], s_a[4][DHEAD];
    int qi = blockIdx.x;             // 0..BHCNT*UTOP-1
    int bh = qi / UTOP;
    int l = Mtop[qi];
    int wid = threadIdx.x >> 5;
    int lane = threadIdx.x & 31;
    const float* q = Q + ((size_t)bh * LSEQ + l) * DHEAD;
    float q0 = q[lane * 2], q1 = q[lane * 2 + 1];
    const float* Kb = K + (size_t)bh * LSEQ * DHEAD;
    const float* Vb = V + (size_t)bh * LSEQ * DHEAD;

    int beg = wid * VSLICE, end = beg + VSLICE;
    // 4 independent online accumulators (break serial chain)
    float m[4], sa[4], a0[4], a1[4];
#pragma unroll
    for (int j = 0; j < 4; j++) { m[j] = NEG_INF; sa[j] = 0.f; a0[j] = 0.f; a1[j] = 0.f; }

#pragma unroll 1
    for (int k0 = beg; k0 < end; k0 += 4) {
        float d[4], v0[4], v1[4];
#pragma unroll
        for (int j = 0; j < 4; j++) {
            int kk = (k0 + j < end) ? (k0 + j) : beg;   // safe addr; masked below
            const float* kr = Kb + (size_t)kk * DHEAD;
            d[j] = q0 * kr[lane * 2] + q1 * kr[lane * 2 + 1];
        }
#pragma unroll
        for (int j = 0; j < 4; j++) d[j] = warp_sum(d[j]) * 0.125f;
#pragma unroll
        for (int j = 0; j < 4; j++) {
            int kk = (k0 + j < end) ? (k0 + j) : beg;
            const float* vr = Vb + (size_t)kk * DHEAD;
            v0[j] = vr[lane * 2];
            v1[j] = vr[lane * 2 + 1];
        }
#pragma unroll
        for (int j = 0; j < 4; j++) {
            if (k0 + j >= end) continue;
            float nm = fmaxf(m[j], d[j]);
            float c = __expf(m[j] - nm);
            float p = __expf(d[j] - nm);
            sa[j] = sa[j] * c + p;
            a0[j] = a0[j] * c + p * v0[j];
            a1[j] = a1[j] * c + p * v1[j];
            m[j] = nm;
        }
    }
    // merge 4 accumulators within warp (uniform m,s; per-lane a)
    float M0 = fmaxf(fmaxf(m[0], m[1]), fmaxf(m[2], m[3]));
    float S = 0.f, A0 = 0.f, A1 = 0.f;
#pragma unroll
    for (int j = 0; j < 4; j++) {
        float c = __expf(m[j] - M0);
        S += sa[j] * c;
        A0 += a0[j] * c;
        A1 += a1[j] * c;
    }
    if (lane == 0) { s_m[wid] = M0; s_s[wid] = S; }
    s_a[wid][lane * 2] = A0;
    s_a[wid][lane * 2 + 1] = A1;
    __syncthreads();
    if (wid == 0) {
        float MM = fmaxf(fmaxf(s_m[0], s_m[1]), fmaxf(s_m[2], s_m[3]));
        float c0 = __expf(s_m[0] - MM), c1 = __expf(s_m[1] - MM);
        float c2 = __expf(s_m[2] - MM), c3 = __expf(s_m[3] - MM);
        float SS = s_s[0] * c0 + s_s[1] * c1 + s_s[2] * c2 + s_s[3] * c3;
        float inv = 1.f / SS;
        int d0 = lane * 2;
        float r0 = (s_a[0][d0] * c0 + s_a[1][d0] * c1 + s_a[2][d0] * c2 + s_a[3][d0] * c3) * inv;
        int d1 = d0 + 1;
        float r1 = (s_a[0][d1] * c0 + s_a[1][d1] * c1 + s_a[2][d1] * c2 + s_a[3][d1] * c3) * inv;
        upd[(size_t)qi * DHEAD + d0] = r0;
        upd[(size_t)qi * DHEAD + d1] = r1;
    }
}

// ---------------- ctx fill (broadcast vmean) ----------------
__global__ void fill_ctx_kernel(const float* __restrict__ vmean, float* __restrict__ ctx) {
    int idx = blockIdx.x * blockDim.x + threadIdx.x;
    if (idx >= M2 * HID) return;
    int c = idx & 127;
    int m = idx >> 7;
    int b = m / LSEQ;
    int h = c >> 6, d = c & 63;
    ctx[idx] = vmean[(b * NHEAD + h) * DHEAD + d];
}

// ---------------- scatter upd rows ----------------
__global__ void scatter_kernel(const float* __restrict__ upd, const int* __restrict__ Mtop,
                               float* __restrict__ ctx) {
    int idx = blockIdx.x * blockDim.x + threadIdx.x;
    if (idx >= BHCNT * UTOP * DHEAD) return;
    int d = idx & 63;
    int r = idx >> 6;
    int bh = r / UTOP;
    int b = bh / NHEAD, h = bh % NHEAD;
    int l = Mtop[r];
    ctx[((size_t)(b * LSEQ + l)) * HID + h * DHEAD + d] = upd[idx];
}

// ---------------- launch ----------------
extern "C" void kernel_launch(void* const* d_in, const int* in_sizes, int n_in,
                              void* d_out, int out_size) {
    const float* x       = (const float*)d_in[0];
    const float* conv1_w = (const float*)d_in[1];
    const float* conv1_b = (const float*)d_in[2];
    const float* conv2_w = (const float*)d_in[3];
    const float* conv2_b = (const float*)d_in[4];
    const float* wq = (const float*)d_in[5];
    const float* bq = (const float*)d_in[6];
    const float* wk = (const float*)d_in[7];
    const float* bk = (const float*)d_in[8];
    const float* wv = (const float*)d_in[9];
    const float* bv = (const float*)d_in[10];
    const float* wo = (const float*)d_in[11];
    const float* bo = (const float*)d_in[12];
    const int* index_sample = (const int*)d_in[13];
    float* out = (float*)d_out;

    float *xcl, *h1cl, *seq, *Qp, *Kp, *Vp, *ctx, *Mv, *updv, *vmeanv;
    float *B1, *B2, *wqkvT, *woT;
    int *mtop;
    cudaGetSymbolAddress((void**)&xcl, g_xcl);
    cudaGetSymbolAddress((void**)&h1cl, g_h1cl);
    cudaGetSymbolAddress((void**)&seq, g_seq);
    cudaGetSymbolAddress((void**)&Qp, g_Q);
    cudaGetSymbolAddress((void**)&Kp, g_K);
    cudaGetSymbolAddress((void**)&Vp, g_V);
    cudaGetSymbolAddress((void**)&ctx, g_ctx);
    cudaGetSymbolAddress((void**)&Mv, g_M);
    cudaGetSymbolAddress((void**)&mtop, g_Mtop);
    cudaGetSymbolAddress((void**)&updv, g_upd);
    cudaGetSymbolAddress((void**)&vmeanv, g_vmean);
    cudaGetSymbolAddress((void**)&B1, g_B1);
    cudaGetSymbolAddress((void**)&B2, g_B2);
    cudaGetSymbolAddress((void**)&wqkvT, g_wqkvT);
    cudaGetSymbolAddress((void**)&woT, g_woT);

    cudaFuncSetAttribute(gemm_tc_kernel<1, K1, true>,
                         cudaFuncAttributeMaxDynamicSharedMemorySize, GEMM_SMEM_BYTES);
    cudaFuncSetAttribute(gemm_tc_kernel<2, K2, true>,
                         cudaFuncAttributeMaxDynamicSharedMemorySize, GEMM_SMEM_BYTES);
    cudaFuncSetAttribute(gemm_tc_kernel<0, HID, false>,
                         cudaFuncAttributeMaxDynamicSharedMemorySize, GEMM_SMEM_BYTES);
    cudaFuncSetAttribute(gemm_qkv_kernel<0>,
                         cudaFuncAttributeMaxDynamicSharedMemorySize, GEMM_SMEM_BYTES);

    // fused prep
    prep_kernel<<<(PREP_S4 + 255) / 256, 256>>>(x, conv1_w, conv2_w, wq, wk, wv, wo,
                                                xcl, B1, B2, wqkvT, woT);

    // conv1 -> h1cl (NHWC row-major), relu
    gemm_tc_kernel<1, K1, true>
        <<<(M1 + 127) / 128, 256, GEMM_SMEM_BYTES>>>(xcl, B1, conv1_b, h1cl, M1);

    // conv2 -> seq, relu
    gemm_tc_kernel<2, K2, true>
        <<<(M2 + 127) / 128, 256, GEMM_SMEM_BYTES>>>(h1cl, B2, conv2_b, seq, M2);

    // fused QKV
    gemm_qkv_kernel<0>
        <<<(M2 + 127) / 128, 256, GEMM_SMEM_BYTES>>>(seq, wqkvT, bq, bk, bv, Qp, Kp, Vp, M2);

    // sampled scores -> M
    {
        int warps = BHCNT * LSEQ;
        sampled_m_kernel<<<(warps + 7) / 8, 256>>>(Qp, Kp, index_sample, Mv);
    }

    topk_kernel<<<BHCNT, 256>>>(Mv, mtop);
    vmean_kernel<<<BHCNT, 256>>>(Vp, vmeanv);

    attn_kernel<<<BHCNT * UTOP, 128>>>(Qp, Kp, Vp, mtop, updv);

    fill_ctx_kernel<<<(M2 * HID + 255) / 256, 256>>>(vmeanv, ctx);
    scatter_kernel<<<(BHCNT * UTOP * DHEAD + 255) / 256, 256>>>(updv, mtop, ctx);

    // final projection
    gemm_tc_kernel<0, HID, false>
        <<<(M2 + 127) / 128, 256, GEMM_SMEM_BYTES>>>(ctx, woT, bo, out, M2);
}